// round 1
// baseline (speedup 1.0000x reference)
#include <cuda_runtime.h>
#include <math.h>

// ---------------------------------------------------------------------------
// Problem constants (Gemma3Attention): B=2, T=1024, S=4096, HIDDEN=2560,
// HEADS=8, KV_HEADS=4, HEAD_DIM=256, WINDOW=1024, SCALE=256^-0.5
// Key fact: valid keys = [cache_index, cache_index+T) exactly (T==WINDOW),
// so attention runs ONLY over the newly projected K/V tokens.
// ---------------------------------------------------------------------------
#define BB   2
#define TT   1024
#define SSZ  4096
#define HID  2560
#define NH   8
#define NKV  4
#define HD   256
#define BT   (BB * TT)            // 2048
#define ATT_SCALE 0.0625f         // 256^-0.5

// ---------------- scratch (device globals; no allocation allowed) ----------
__device__ float g_q  [(long long)BT * NH  * HD];   // qkv proj outputs (b*T+t, h*D+d)
__device__ float g_k  [(long long)BT * NKV * HD];
__device__ float g_v  [(long long)BT * NKV * HD];
__device__ float g_qp [(long long)BB * NH  * TT * HD];  // post norm+rope, (b,h,t,d)
__device__ float g_kp [(long long)BB * NKV * TT * HD];
__device__ float g_vp [(long long)BB * NKV * TT * HD];
__device__ float g_sc [(long long)BB * NH  * TT * TT];  // attention scores/probs
__device__ float g_ctx[(long long)BT * NH  * HD];       // attn output, (b*T+t, h*D+d)

// ---------------------------------------------------------------------------
// Tiled SGEMM, row-major. C = A(MxK) @ B(KxN)  (NN)  or  A(MxK) @ B(NxK)^T (NT)
// Block tile 128x128, K-step 8, 256 threads, 8x8 per-thread microtile.
// Batched over blockIdx.z with generic offset:  off = (z/div)*s1 + (z%div)*s2
// lda = K, ldb = N (NN) / K (NT), ldc passed explicitly.
// All problem dims are multiples of the tiles -> no bounds checks.
// ---------------------------------------------------------------------------
#define BM 128
#define BN 128
#define BK 8
#define TM 8
#define TN 8

__global__ __launch_bounds__(256) void sgemm_nn(
    const float* __restrict__ A, const float* __restrict__ Bm, float* __restrict__ C,
    int M, int N, int K, int ldc,
    long long aDiv, long long aS1, long long aS2,
    long long bDiv, long long bS1, long long bS2,
    long long cDiv, long long cS1, long long cS2)
{
    long long z = blockIdx.z;
    A  += (z / aDiv) * aS1 + (z % aDiv) * aS2;
    Bm += (z / bDiv) * bS1 + (z % bDiv) * bS2;
    C  += (z / cDiv) * cS1 + (z % cDiv) * cS2;

    __shared__ float As[BK][BM];
    __shared__ float Bs[BK][BN];

    int tid  = threadIdx.x;
    int brow = blockIdx.y * BM;
    int bcol = blockIdx.x * BN;

    int aRow = tid >> 1;            // 0..127
    int aCol = (tid & 1) * 4;       // 0 or 4
    int bRow = tid >> 5;            // 0..7
    int bCol = (tid & 31) * 4;      // 0..124

    int trow = (tid >> 4) * TM;     // 0..120
    int tcol = (tid & 15) * TN;

    float acc[TM][TN] = {};

    for (int k0 = 0; k0 < K; k0 += BK) {
        float4 av = *(const float4*)(A + (long long)(brow + aRow) * K + k0 + aCol);
        As[aCol + 0][aRow] = av.x;
        As[aCol + 1][aRow] = av.y;
        As[aCol + 2][aRow] = av.z;
        As[aCol + 3][aRow] = av.w;
        float4 bv = *(const float4*)(Bm + (long long)(k0 + bRow) * N + bcol + bCol);
        *(float4*)&Bs[bRow][bCol] = bv;
        __syncthreads();

        #pragma unroll
        for (int kk = 0; kk < BK; kk++) {
            float ar[TM], br[TN];
            *(float4*)&ar[0] = *(const float4*)&As[kk][trow];
            *(float4*)&ar[4] = *(const float4*)&As[kk][trow + 4];
            *(float4*)&br[0] = *(const float4*)&Bs[kk][tcol];
            *(float4*)&br[4] = *(const float4*)&Bs[kk][tcol + 4];
            #pragma unroll
            for (int i = 0; i < TM; i++)
                #pragma unroll
                for (int j = 0; j < TN; j++)
                    acc[i][j] += ar[i] * br[j];
        }
        __syncthreads();
    }

    #pragma unroll
    for (int i = 0; i < TM; i++) {
        #pragma unroll
        for (int j = 0; j < TN; j += 4) {
            float4 cv = make_float4(acc[i][j], acc[i][j+1], acc[i][j+2], acc[i][j+3]);
            *(float4*)(C + (long long)(brow + trow + i) * ldc + bcol + tcol + j) = cv;
        }
    }
}

__global__ __launch_bounds__(256) void sgemm_nt(
    const float* __restrict__ A, const float* __restrict__ Bm, float* __restrict__ C,
    int M, int N, int K, int ldc,
    long long aDiv, long long aS1, long long aS2,
    long long bDiv, long long bS1, long long bS2,
    long long cDiv, long long cS1, long long cS2)
{
    long long z = blockIdx.z;
    A  += (z / aDiv) * aS1 + (z % aDiv) * aS2;
    Bm += (z / bDiv) * bS1 + (z % bDiv) * bS2;
    C  += (z / cDiv) * cS1 + (z % cDiv) * cS2;

    __shared__ float As[BK][BM];
    __shared__ float Bs[BK][BN];

    int tid  = threadIdx.x;
    int brow = blockIdx.y * BM;
    int bcol = blockIdx.x * BN;

    int aRow = tid >> 1;
    int aCol = (tid & 1) * 4;

    int trow = (tid >> 4) * TM;
    int tcol = (tid & 15) * TN;

    float acc[TM][TN] = {};

    for (int k0 = 0; k0 < K; k0 += BK) {
        float4 av = *(const float4*)(A + (long long)(brow + aRow) * K + k0 + aCol);
        As[aCol + 0][aRow] = av.x;
        As[aCol + 1][aRow] = av.y;
        As[aCol + 2][aRow] = av.z;
        As[aCol + 3][aRow] = av.w;
        // B is (N x K) row-major; Bs[kk][n] = B[bcol+n][k0+kk]
        float4 bv = *(const float4*)(Bm + (long long)(bcol + aRow) * K + k0 + aCol);
        Bs[aCol + 0][aRow] = bv.x;
        Bs[aCol + 1][aRow] = bv.y;
        Bs[aCol + 2][aRow] = bv.z;
        Bs[aCol + 3][aRow] = bv.w;
        __syncthreads();

        #pragma unroll
        for (int kk = 0; kk < BK; kk++) {
            float ar[TM], br[TN];
            *(float4*)&ar[0] = *(const float4*)&As[kk][trow];
            *(float4*)&ar[4] = *(const float4*)&As[kk][trow + 4];
            *(float4*)&br[0] = *(const float4*)&Bs[kk][tcol];
            *(float4*)&br[4] = *(const float4*)&Bs[kk][tcol + 4];
            #pragma unroll
            for (int i = 0; i < TM; i++)
                #pragma unroll
                for (int j = 0; j < TN; j++)
                    acc[i][j] += ar[i] * br[j];
        }
        __syncthreads();
    }

    #pragma unroll
    for (int i = 0; i < TM; i++) {
        #pragma unroll
        for (int j = 0; j < TN; j += 4) {
            float4 cv = make_float4(acc[i][j], acc[i][j+1], acc[i][j+2], acc[i][j+3]);
            *(float4*)(C + (long long)(brow + trow + i) * ldc + bcol + tcol + j) = cv;
        }
    }
}

// ---------------------------------------------------------------------------
// RMSNorm + RoPE + relayout + cache scatter.
// grid = (BT, 16): blockIdx.y 0..7 -> Q heads, 8..11 -> K heads, 12..15 -> V heads
// 128 threads: thread j handles dims (j, j+128)  (RoPE half-split pairs)
// ---------------------------------------------------------------------------
__device__ __forceinline__ float block_sum_128(float v) {
    #pragma unroll
    for (int o = 16; o > 0; o >>= 1) v += __shfl_xor_sync(0xffffffffu, v, o);
    __shared__ float sh[4];
    int w = threadIdx.x >> 5;
    if ((threadIdx.x & 31) == 0) sh[w] = v;
    __syncthreads();
    return sh[0] + sh[1] + sh[2] + sh[3];
}

__global__ void normrope_kernel(
    const float* __restrict__ qw, const float* __restrict__ kw,
    const int* __restrict__ posp, const int* __restrict__ cip,
    float* __restrict__ outk, float* __restrict__ outv)
{
    int bt  = blockIdx.x;
    int b   = bt / TT, t = bt - b * TT;
    int hsl = blockIdx.y;
    int tid = threadIdx.x;   // 0..127

    if (hsl >= NH + NKV) {
        // ---- V: pure relayout + cache scatter ----
        int h = hsl - NH - NKV;
        int ci = *cip;
        const float* src = g_v + (long long)bt * (NKV * HD) + h * HD;
        float v1 = src[tid], v2 = src[tid + 128];
        float* dst = g_vp + (((long long)b * NKV + h) * TT + t) * HD;
        dst[tid] = v1; dst[tid + 128] = v2;
        float* dc = outv + (((long long)b * NKV + h) * SSZ + ci + t) * HD;
        dc[tid] = v1; dc[tid + 128] = v2;
        return;
    }

    bool isQ = (hsl < NH);
    int  h   = isQ ? hsl : hsl - NH;
    const float* src = isQ ? (g_q + (long long)bt * (NH  * HD) + h * HD)
                           : (g_k + (long long)bt * (NKV * HD) + h * HD);
    const float* w = isQ ? qw : kw;

    float v1 = src[tid], v2 = src[tid + 128];
    float ss = block_sum_128(v1 * v1 + v2 * v2);
    float r  = rsqrtf(ss * (1.0f / HD) + 1e-6f);
    float x1 = v1 * r * (1.0f + w[tid]);
    float x2 = v2 * r * (1.0f + w[tid + 128]);

    // RoPE: inv_freq = 10000^(-j/128), ang = pos * inv_freq (fp32 product, like
    // the reference), then reduce mod 2pi in double so cosf/sinf stay accurate
    // even under fast-math.
    int pos = *posp + t;
    float inv = (float)pow(10000.0, -(double)tid / 128.0);
    float ang = (float)pos * inv;
    double da  = (double)ang;
    double red = da - floor(da * 0.159154943091895335768883763373) *
                      6.283185307179586476925286766559;
    float c = cosf((float)red), s = sinf((float)red);

    float o1 = x1 * c - x2 * s;
    float o2 = x2 * c + x1 * s;

    if (isQ) {
        o1 *= ATT_SCALE; o2 *= ATT_SCALE;   // fold softmax scale into Q
        float* dst = g_qp + (((long long)b * NH + h) * TT + t) * HD;
        dst[tid] = o1; dst[tid + 128] = o2;
    } else {
        float* dst = g_kp + (((long long)b * NKV + h) * TT + t) * HD;
        dst[tid] = o1; dst[tid + 128] = o2;
        int ci = *cip;
        float* dc = outk + (((long long)b * NKV + h) * SSZ + ci + t) * HD;
        dc[tid] = o1; dc[tid + 128] = o2;
    }
}

// ---------------------------------------------------------------------------
// Row softmax over 1024 keys (window fully valid -> plain dense softmax).
// One block (256 threads) per row, float4 per thread, in-place.
// ---------------------------------------------------------------------------
__global__ __launch_bounds__(256) void softmax_kernel(float* __restrict__ sc)
{
    long long row = blockIdx.x;
    float* p = sc + row * TT;
    int tid = threadIdx.x;

    float4 v = ((float4*)p)[tid];
    float m = fmaxf(fmaxf(v.x, v.y), fmaxf(v.z, v.w));
    #pragma unroll
    for (int o = 16; o > 0; o >>= 1) m = fmaxf(m, __shfl_xor_sync(0xffffffffu, m, o));
    __shared__ float sm[8];
    int w = tid >> 5;
    if ((tid & 31) == 0) sm[w] = m;
    __syncthreads();
    m = fmaxf(fmaxf(fmaxf(sm[0], sm[1]), fmaxf(sm[2], sm[3])),
              fmaxf(fmaxf(sm[4], sm[5]), fmaxf(sm[6], sm[7])));

    float e0 = expf(v.x - m), e1 = expf(v.y - m), e2 = expf(v.z - m), e3 = expf(v.w - m);
    float sum = e0 + e1 + e2 + e3;
    #pragma unroll
    for (int o = 16; o > 0; o >>= 1) sum += __shfl_xor_sync(0xffffffffu, sum, o);
    __shared__ float s2[8];
    if ((tid & 31) == 0) s2[w] = sum;
    __syncthreads();
    sum = s2[0] + s2[1] + s2[2] + s2[3] + s2[4] + s2[5] + s2[6] + s2[7];

    float inv = 1.0f / sum;
    v.x = e0 * inv; v.y = e1 * inv; v.z = e2 * inv; v.w = e3 * inv;
    ((float4*)p)[tid] = v;
}

// ---------------------------------------------------------------------------
// kernel_launch: graph-capturable sequence on the default stream.
// Inputs (metadata order): x, k_cache, v_cache, wq, wk, wv, wo,
//                          q_norm_w, k_norm_w, pos_offset, cache_index
// Output: [ out (B,T,HID) | k_new (B,NKV,S,HD) | v_new (B,NKV,S,HD) ] fp32
// ---------------------------------------------------------------------------
extern "C" void kernel_launch(void* const* d_in, const int* in_sizes, int n_in,
                              void* d_out, int out_size)
{
    const float* x       = (const float*)d_in[0];
    const float* k_cache = (const float*)d_in[1];
    const float* v_cache = (const float*)d_in[2];
    const float* wq      = (const float*)d_in[3];
    const float* wk      = (const float*)d_in[4];
    const float* wv      = (const float*)d_in[5];
    const float* wo      = (const float*)d_in[6];
    const float* qw      = (const float*)d_in[7];
    const float* kw      = (const float*)d_in[8];
    const int*   posp    = (const int*)d_in[9];
    const int*   cip     = (const int*)d_in[10];

    float* out  = (float*)d_out;
    float* outk = out  + (long long)BB * TT * HID;
    float* outv = outk + (long long)BB * NKV * SSZ * HD;

    float *pq, *pk, *pv, *pqp, *pkp, *pvp, *psc, *pctx;
    cudaGetSymbolAddress((void**)&pq,   g_q);
    cudaGetSymbolAddress((void**)&pk,   g_k);
    cudaGetSymbolAddress((void**)&pv,   g_v);
    cudaGetSymbolAddress((void**)&pqp,  g_qp);
    cudaGetSymbolAddress((void**)&pkp,  g_kp);
    cudaGetSymbolAddress((void**)&pvp,  g_vp);
    cudaGetSymbolAddress((void**)&psc,  g_sc);
    cudaGetSymbolAddress((void**)&pctx, g_ctx);

    // Cache copies (slice overwritten later by normrope, same stream order).
    size_t cacheBytes = sizeof(float) * (size_t)BB * NKV * SSZ * HD;
    cudaMemcpyAsync(outk, k_cache, cacheBytes, cudaMemcpyDeviceToDevice, 0);
    cudaMemcpyAsync(outv, v_cache, cacheBytes, cudaMemcpyDeviceToDevice, 0);

    dim3 blk(256);

    // QKV projections
    sgemm_nn<<<dim3((NH  * HD) / BN, BT / BM, 1), blk>>>(
        x, wq, pq, BT, NH * HD, HID, NH * HD,
        1, 0, 0,  1, 0, 0,  1, 0, 0);
    sgemm_nn<<<dim3((NKV * HD) / BN, BT / BM, 1), blk>>>(
        x, wk, pk, BT, NKV * HD, HID, NKV * HD,
        1, 0, 0,  1, 0, 0,  1, 0, 0);
    sgemm_nn<<<dim3((NKV * HD) / BN, BT / BM, 1), blk>>>(
        x, wv, pv, BT, NKV * HD, HID, NKV * HD,
        1, 0, 0,  1, 0, 0,  1, 0, 0);

    // RMSNorm + RoPE + relayout + cache slice scatter
    normrope_kernel<<<dim3(BT, NH + NKV + NKV), 128>>>(qw, kw, posp, cip, outk, outv);

    // Scores: per (b,h): (T x D) @ (T x D)^T.  z = b*NH + h; kv tile = z/2.
    sgemm_nt<<<dim3(TT / BN, TT / BM, BB * NH), blk>>>(
        pqp, pkp, psc, TT, TT, HD, TT,
        1, (long long)TT * HD, 0,
        2, (long long)TT * HD, 0,
        1, (long long)TT * TT, 0);

    // Softmax over the 1024 valid keys
    softmax_kernel<<<(long long)BB * NH * TT, 256>>>(psc);

    // O = P @ V, written directly into (b*T+t, h*D+d) layout (ldc = NH*HD)
    sgemm_nn<<<dim3(HD / BN, TT / BM, BB * NH), blk>>>(
        psc, pvp, pctx, TT, HD, TT, NH * HD,
        1, (long long)TT * TT, 0,
        2, (long long)TT * HD, 0,
        NH, (long long)TT * NH * HD, (long long)HD);

    // Output projection
    sgemm_nn<<<dim3(HID / BN, BT / BM, 1), blk>>>(
        pctx, wo, out, BT, HID, NH * HD, HID,
        1, 0, 0,  1, 0, 0,  1, 0, 0);
}

// round 2
// speedup vs baseline: 1.3957x; 1.3957x over previous
#include <cuda_runtime.h>
#include <math.h>

// ---------------------------------------------------------------------------
// Problem constants (Gemma3Attention): B=2, T=1024, S=4096, HIDDEN=2560,
// HEADS=8, KV_HEADS=4, HEAD_DIM=256, WINDOW=1024, SCALE=256^-0.5
// Key fact: valid keys = [cache_index, cache_index+T) exactly (T==WINDOW),
// so attention runs ONLY over the newly projected K/V tokens.
// ---------------------------------------------------------------------------
#define BB   2
#define TT   1024
#define SSZ  4096
#define HID  2560
#define NH   8
#define NKV  4
#define HD   256
#define BT   (BB * TT)            // 2048
#define ATT_SCALE 0.0625f         // 256^-0.5

// ---------------- scratch (device globals; no allocation allowed) ----------
__device__ float g_q  [(long long)BT * NH  * HD];   // qkv proj outputs (b*T+t, h*D+d)
__device__ float g_k  [(long long)BT * NKV * HD];
__device__ float g_v  [(long long)BT * NKV * HD];
__device__ float g_qp [(long long)BB * NH  * TT * HD];  // post norm+rope, (b,h,t,d)
__device__ float g_kp [(long long)BB * NKV * TT * HD];
__device__ float g_vp [(long long)BB * NKV * TT * HD];
__device__ float g_sc [(long long)BB * NH  * TT * TT];  // attention scores/probs
__device__ float g_ctx[(long long)BT * NH  * HD];       // attn output, (b*T+t, h*D+d)
__device__ float g_invfreq[128];                        // RoPE inv_freq table

// ---------------------------------------------------------------------------
// inv_freq table: 128 double pows, once per launch (microseconds).
// ---------------------------------------------------------------------------
__global__ void init_invfreq_kernel() {
    int j = threadIdx.x;
    g_invfreq[j] = (float)pow(10000.0, -(double)j / 128.0);
}

// ---------------------------------------------------------------------------
// Tiled SGEMM, row-major. C = A(MxK) @ B(KxN)  (NN)  or  A(MxK) @ B(NxK)^T (NT)
// Block tile 128x128, K-step 8, 256 threads, 8x8 per-thread microtile.
// Software-pipelined: next K-slice global loads issued before current compute.
// Batched over blockIdx.z with generic offset:  off = (z/div)*s1 + (z%div)*s2
// All problem dims are multiples of the tiles -> no bounds checks.
// ---------------------------------------------------------------------------
#define BM 128
#define BN 128
#define BK 8
#define TM 8
#define TN 8

__global__ __launch_bounds__(256) void sgemm_nn(
    const float* __restrict__ A, const float* __restrict__ Bm, float* __restrict__ C,
    int M, int N, int K, int ldc,
    long long aDiv, long long aS1, long long aS2,
    long long bDiv, long long bS1, long long bS2,
    long long cDiv, long long cS1, long long cS2)
{
    long long z = blockIdx.z;
    A  += (z / aDiv) * aS1 + (z % aDiv) * aS2;
    Bm += (z / bDiv) * bS1 + (z % bDiv) * bS2;
    C  += (z / cDiv) * cS1 + (z % cDiv) * cS2;

    __shared__ float As[BK][BM];
    __shared__ float Bs[BK][BN];

    int tid  = threadIdx.x;
    int brow = blockIdx.y * BM;
    int bcol = blockIdx.x * BN;

    int aRow = tid >> 1;            // 0..127
    int aCol = (tid & 1) * 4;       // 0 or 4
    int bRow = tid >> 5;            // 0..7
    int bCol = (tid & 31) * 4;      // 0..124

    int trow = (tid >> 4) * TM;     // 0..120
    int tcol = (tid & 15) * TN;

    const float* aPtr = A + (long long)(brow + aRow) * K + aCol;
    const float* bPtr = Bm + (long long)bRow * N + bcol + bCol;

    float acc[TM][TN] = {};

    float4 av = *(const float4*)(aPtr);
    float4 bv = *(const float4*)(bPtr);

    for (int k0 = 0; k0 < K; k0 += BK) {
        As[aCol + 0][aRow] = av.x;
        As[aCol + 1][aRow] = av.y;
        As[aCol + 2][aRow] = av.z;
        As[aCol + 3][aRow] = av.w;
        *(float4*)&Bs[bRow][bCol] = bv;
        __syncthreads();

        if (k0 + BK < K) {              // prefetch next slice into registers
            av = *(const float4*)(aPtr + k0 + BK);
            bv = *(const float4*)(bPtr + (long long)(k0 + BK) * N);
        }

        #pragma unroll
        for (int kk = 0; kk < BK; kk++) {
            float ar[TM], br[TN];
            *(float4*)&ar[0] = *(const float4*)&As[kk][trow];
            *(float4*)&ar[4] = *(const float4*)&As[kk][trow + 4];
            *(float4*)&br[0] = *(const float4*)&Bs[kk][tcol];
            *(float4*)&br[4] = *(const float4*)&Bs[kk][tcol + 4];
            #pragma unroll
            for (int i = 0; i < TM; i++)
                #pragma unroll
                for (int j = 0; j < TN; j++)
                    acc[i][j] += ar[i] * br[j];
        }
        __syncthreads();
    }

    #pragma unroll
    for (int i = 0; i < TM; i++) {
        #pragma unroll
        for (int j = 0; j < TN; j += 4) {
            float4 cv = make_float4(acc[i][j], acc[i][j+1], acc[i][j+2], acc[i][j+3]);
            *(float4*)(C + (long long)(brow + trow + i) * ldc + bcol + tcol + j) = cv;
        }
    }
}

__global__ __launch_bounds__(256) void sgemm_nt(
    const float* __restrict__ A, const float* __restrict__ Bm, float* __restrict__ C,
    int M, int N, int K, int ldc,
    long long aDiv, long long aS1, long long aS2,
    long long bDiv, long long bS1, long long bS2,
    long long cDiv, long long cS1, long long cS2)
{
    long long z = blockIdx.z;
    A  += (z / aDiv) * aS1 + (z % aDiv) * aS2;
    Bm += (z / bDiv) * bS1 + (z % bDiv) * bS2;
    C  += (z / cDiv) * cS1 + (z % cDiv) * cS2;

    __shared__ float As[BK][BM];
    __shared__ float Bs[BK][BN];

    int tid  = threadIdx.x;
    int brow = blockIdx.y * BM;
    int bcol = blockIdx.x * BN;

    int aRow = tid >> 1;
    int aCol = (tid & 1) * 4;

    int trow = (tid >> 4) * TM;
    int tcol = (tid & 15) * TN;

    const float* aPtr = A + (long long)(brow + aRow) * K + aCol;
    const float* bPtr = Bm + (long long)(bcol + aRow) * K + aCol;

    float acc[TM][TN] = {};

    float4 av = *(const float4*)(aPtr);
    float4 bv = *(const float4*)(bPtr);

    for (int k0 = 0; k0 < K; k0 += BK) {
        As[aCol + 0][aRow] = av.x;
        As[aCol + 1][aRow] = av.y;
        As[aCol + 2][aRow] = av.z;
        As[aCol + 3][aRow] = av.w;
        // B is (N x K) row-major; Bs[kk][n] = B[bcol+n][k0+kk]
        Bs[aCol + 0][aRow] = bv.x;
        Bs[aCol + 1][aRow] = bv.y;
        Bs[aCol + 2][aRow] = bv.z;
        Bs[aCol + 3][aRow] = bv.w;
        __syncthreads();

        if (k0 + BK < K) {
            av = *(const float4*)(aPtr + k0 + BK);
            bv = *(const float4*)(bPtr + k0 + BK);
        }

        #pragma unroll
        for (int kk = 0; kk < BK; kk++) {
            float ar[TM], br[TN];
            *(float4*)&ar[0] = *(const float4*)&As[kk][trow];
            *(float4*)&ar[4] = *(const float4*)&As[kk][trow + 4];
            *(float4*)&br[0] = *(const float4*)&Bs[kk][tcol];
            *(float4*)&br[4] = *(const float4*)&Bs[kk][tcol + 4];
            #pragma unroll
            for (int i = 0; i < TM; i++)
                #pragma unroll
                for (int j = 0; j < TN; j++)
                    acc[i][j] += ar[i] * br[j];
        }
        __syncthreads();
    }

    #pragma unroll
    for (int i = 0; i < TM; i++) {
        #pragma unroll
        for (int j = 0; j < TN; j += 4) {
            float4 cv = make_float4(acc[i][j], acc[i][j+1], acc[i][j+2], acc[i][j+3]);
            *(float4*)(C + (long long)(brow + trow + i) * ldc + bcol + tcol + j) = cv;
        }
    }
}

// ---------------------------------------------------------------------------
// RMSNorm + RoPE + relayout + cache scatter.
// grid = (BT, 16): blockIdx.y 0..7 -> Q heads, 8..11 -> K heads, 12..15 -> V heads
// 128 threads: thread j handles dims (j, j+128)  (RoPE half-split pairs)
// ---------------------------------------------------------------------------
__device__ __forceinline__ float block_sum_128(float v) {
    #pragma unroll
    for (int o = 16; o > 0; o >>= 1) v += __shfl_xor_sync(0xffffffffu, v, o);
    __shared__ float sh[4];
    int w = threadIdx.x >> 5;
    if ((threadIdx.x & 31) == 0) sh[w] = v;
    __syncthreads();
    return sh[0] + sh[1] + sh[2] + sh[3];
}

__global__ void normrope_kernel(
    const float* __restrict__ qw, const float* __restrict__ kw,
    const int* __restrict__ posp, const int* __restrict__ cip,
    float* __restrict__ outk, float* __restrict__ outv)
{
    int bt  = blockIdx.x;
    int b   = bt / TT, t = bt - b * TT;
    int hsl = blockIdx.y;
    int tid = threadIdx.x;   // 0..127

    if (hsl >= NH + NKV) {
        // ---- V: pure relayout + cache scatter ----
        int h = hsl - NH - NKV;
        int ci = *cip;
        const float* src = g_v + (long long)bt * (NKV * HD) + h * HD;
        float v1 = src[tid], v2 = src[tid + 128];
        float* dst = g_vp + (((long long)b * NKV + h) * TT + t) * HD;
        dst[tid] = v1; dst[tid + 128] = v2;
        float* dc = outv + (((long long)b * NKV + h) * SSZ + ci + t) * HD;
        dc[tid] = v1; dc[tid + 128] = v2;
        return;
    }

    bool isQ = (hsl < NH);
    int  h   = isQ ? hsl : hsl - NH;
    const float* src = isQ ? (g_q + (long long)bt * (NH  * HD) + h * HD)
                           : (g_k + (long long)bt * (NKV * HD) + h * HD);
    const float* w = isQ ? qw : kw;

    float v1 = src[tid], v2 = src[tid + 128];
    float ss = block_sum_128(v1 * v1 + v2 * v2);
    float r  = rsqrtf(ss * (1.0f / HD) + 1e-6f);
    float x1 = v1 * r * (1.0f + w[tid]);
    float x2 = v2 * r * (1.0f + w[tid + 128]);

    // RoPE: inv_freq from the precomputed table (double pow done once in the
    // init kernel). Angle formed in fp32 like the reference, then reduced
    // mod 2pi in double (4 cheap FP64 ops) so cosf/sinf stay accurate even
    // under fast-math.
    int pos = *posp + t;
    float inv = g_invfreq[tid];
    float ang = (float)pos * inv;
    double da  = (double)ang;
    double red = da - floor(da * 0.159154943091895335768883763373) *
                      6.283185307179586476925286766559;
    float c = cosf((float)red), s = sinf((float)red);

    float o1 = x1 * c - x2 * s;
    float o2 = x2 * c + x1 * s;

    if (isQ) {
        o1 *= ATT_SCALE; o2 *= ATT_SCALE;   // fold softmax scale into Q
        float* dst = g_qp + (((long long)b * NH + h) * TT + t) * HD;
        dst[tid] = o1; dst[tid + 128] = o2;
    } else {
        float* dst = g_kp + (((long long)b * NKV + h) * TT + t) * HD;
        dst[tid] = o1; dst[tid + 128] = o2;
        int ci = *cip;
        float* dc = outk + (((long long)b * NKV + h) * SSZ + ci + t) * HD;
        dc[tid] = o1; dc[tid + 128] = o2;
    }
}

// ---------------------------------------------------------------------------
// Row softmax over 1024 keys (window fully valid -> plain dense softmax).
// One block (256 threads) per row, float4 per thread, in-place.
// ---------------------------------------------------------------------------
__global__ __launch_bounds__(256) void softmax_kernel(float* __restrict__ sc)
{
    long long row = blockIdx.x;
    float* p = sc + row * TT;
    int tid = threadIdx.x;

    float4 v = ((float4*)p)[tid];
    float m = fmaxf(fmaxf(v.x, v.y), fmaxf(v.z, v.w));
    #pragma unroll
    for (int o = 16; o > 0; o >>= 1) m = fmaxf(m, __shfl_xor_sync(0xffffffffu, m, o));
    __shared__ float sm[8];
    int w = tid >> 5;
    if ((tid & 31) == 0) sm[w] = m;
    __syncthreads();
    m = fmaxf(fmaxf(fmaxf(sm[0], sm[1]), fmaxf(sm[2], sm[3])),
              fmaxf(fmaxf(sm[4], sm[5]), fmaxf(sm[6], sm[7])));

    float e0 = expf(v.x - m), e1 = expf(v.y - m), e2 = expf(v.z - m), e3 = expf(v.w - m);
    float sum = e0 + e1 + e2 + e3;
    #pragma unroll
    for (int o = 16; o > 0; o >>= 1) sum += __shfl_xor_sync(0xffffffffu, sum, o);
    __shared__ float s2[8];
    if ((tid & 31) == 0) s2[w] = sum;
    __syncthreads();
    sum = s2[0] + s2[1] + s2[2] + s2[3] + s2[4] + s2[5] + s2[6] + s2[7];

    float inv = 1.0f / sum;
    v.x = e0 * inv; v.y = e1 * inv; v.z = e2 * inv; v.w = e3 * inv;
    ((float4*)p)[tid] = v;
}

// ---------------------------------------------------------------------------
// kernel_launch: graph-capturable sequence on the default stream.
// Inputs (metadata order): x, k_cache, v_cache, wq, wk, wv, wo,
//                          q_norm_w, k_norm_w, pos_offset, cache_index
// Output: [ out (B,T,HID) | k_new (B,NKV,S,HD) | v_new (B,NKV,S,HD) ] fp32
// ---------------------------------------------------------------------------
extern "C" void kernel_launch(void* const* d_in, const int* in_sizes, int n_in,
                              void* d_out, int out_size)
{
    const float* x       = (const float*)d_in[0];
    const float* k_cache = (const float*)d_in[1];
    const float* v_cache = (const float*)d_in[2];
    const float* wq      = (const float*)d_in[3];
    const float* wk      = (const float*)d_in[4];
    const float* wv      = (const float*)d_in[5];
    const float* wo      = (const float*)d_in[6];
    const float* qw      = (const float*)d_in[7];
    const float* kw      = (const float*)d_in[8];
    const int*   posp    = (const int*)d_in[9];
    const int*   cip     = (const int*)d_in[10];

    float* out  = (float*)d_out;
    float* outk = out  + (long long)BB * TT * HID;
    float* outv = outk + (long long)BB * NKV * SSZ * HD;

    float *pq, *pk, *pv, *pqp, *pkp, *pvp, *psc, *pctx;
    cudaGetSymbolAddress((void**)&pq,   g_q);
    cudaGetSymbolAddress((void**)&pk,   g_k);
    cudaGetSymbolAddress((void**)&pv,   g_v);
    cudaGetSymbolAddress((void**)&pqp,  g_qp);
    cudaGetSymbolAddress((void**)&pkp,  g_kp);
    cudaGetSymbolAddress((void**)&pvp,  g_vp);
    cudaGetSymbolAddress((void**)&psc,  g_sc);
    cudaGetSymbolAddress((void**)&pctx, g_ctx);

    // Cache copies (slice overwritten later by normrope, same stream order).
    size_t cacheBytes = sizeof(float) * (size_t)BB * NKV * SSZ * HD;
    cudaMemcpyAsync(outk, k_cache, cacheBytes, cudaMemcpyDeviceToDevice, 0);
    cudaMemcpyAsync(outv, v_cache, cacheBytes, cudaMemcpyDeviceToDevice, 0);

    // RoPE inv_freq table (128 double pows, trivial)
    init_invfreq_kernel<<<1, 128>>>();

    dim3 blk(256);

    // QKV projections
    sgemm_nn<<<dim3((NH  * HD) / BN, BT / BM, 1), blk>>>(
        x, wq, pq, BT, NH * HD, HID, NH * HD,
        1, 0, 0,  1, 0, 0,  1, 0, 0);
    sgemm_nn<<<dim3((NKV * HD) / BN, BT / BM, 1), blk>>>(
        x, wk, pk, BT, NKV * HD, HID, NKV * HD,
        1, 0, 0,  1, 0, 0,  1, 0, 0);
    sgemm_nn<<<dim3((NKV * HD) / BN, BT / BM, 1), blk>>>(
        x, wv, pv, BT, NKV * HD, HID, NKV * HD,
        1, 0, 0,  1, 0, 0,  1, 0, 0);

    // RMSNorm + RoPE + relayout + cache slice scatter
    normrope_kernel<<<dim3(BT, NH + NKV + NKV), 128>>>(qw, kw, posp, cip, outk, outv);

    // Scores: per (b,h): (T x D) @ (T x D)^T.  z = b*NH + h; kv tile = z/2.
    sgemm_nt<<<dim3(TT / BN, TT / BM, BB * NH), blk>>>(
        pqp, pkp, psc, TT, TT, HD, TT,
        1, (long long)TT * HD, 0,
        2, (long long)TT * HD, 0,
        1, (long long)TT * TT, 0);

    // Softmax over the 1024 valid keys
    softmax_kernel<<<(long long)BB * NH * TT, 256>>>(psc);

    // O = P @ V, written directly into (b*T+t, h*D+d) layout (ldc = NH*HD)
    sgemm_nn<<<dim3(HD / BN, TT / BM, BB * NH), blk>>>(
        psc, pvp, pctx, TT, HD, TT, NH * HD,
        1, (long long)TT * TT, 0,
        2, (long long)TT * HD, 0,
        NH, (long long)TT * NH * HD, (long long)HD);

    // Output projection
    sgemm_nn<<<dim3(HID / BN, BT / BM, 1), blk>>>(
        pctx, wo, out, BT, HID, NH * HD, HID,
        1, 0, 0,  1, 0, 0,  1, 0, 0);
}

// round 4
// speedup vs baseline: 3.0058x; 2.1536x over previous
#include <cuda_runtime.h>
#include <cuda_bf16.h>
#include <cstdint>
#include <math.h>

// ---------------------------------------------------------------------------
// Gemma3Attention on GB300 (compute_103 target -> no tcgen05; use mma.sync
// HMMA bf16 with hi/lo split, fp32 accumulate).
// B=2, T=1024, S=4096, HIDDEN=2560, HEADS=8, KV_HEADS=4, HEAD_DIM=256.
// valid keys == [cache_index, cache_index+T) exactly -> attention only over
// the freshly projected K/V tokens.
// ---------------------------------------------------------------------------
#define BB   2
#define TT   1024
#define SSZ  4096
#define HID  2560
#define NH   8
#define NKV  4
#define HD   256
#define BT   (BB * TT)            // 2048
#define QKVN 4096                 // 2048 q + 1024 k + 1024 v cols
#define ATT_SCALE 0.0625f

// ---------------- scratch (device globals) ---------------------------------
__device__ float          g_qkv [(long long)BT * QKVN];        // fp32 qkv proj
__device__ __nv_bfloat16  g_xh  [(long long)BT * HID];
__device__ __nv_bfloat16  g_xl  [(long long)BT * HID];
__device__ __nv_bfloat16  g_wth [(long long)QKVN * HID];       // [wq;wk;wv]^T
__device__ __nv_bfloat16  g_wtl [(long long)QKVN * HID];
__device__ __nv_bfloat16  g_woth[(long long)HID * (NH * HD)];  // wo^T
__device__ __nv_bfloat16  g_wotl[(long long)HID * (NH * HD)];
__device__ __nv_bfloat16  g_qph [(long long)BB * NH  * TT * HD];
__device__ __nv_bfloat16  g_qpl [(long long)BB * NH  * TT * HD];
__device__ __nv_bfloat16  g_kph [(long long)BB * NKV * TT * HD];
__device__ __nv_bfloat16  g_kpl [(long long)BB * NKV * TT * HD];
__device__ __nv_bfloat16  g_vth [(long long)BB * NKV * HD * TT];  // V^T
__device__ __nv_bfloat16  g_vtl [(long long)BB * NKV * HD * TT];
__device__ float          g_sc  [(long long)BB * NH * TT * TT];
__device__ __nv_bfloat16  g_ph  [(long long)BB * NH * TT * TT];
__device__ __nv_bfloat16  g_pl  [(long long)BB * NH * TT * TT];
__device__ __nv_bfloat16  g_ctxh[(long long)BT * NH * HD];
__device__ __nv_bfloat16  g_ctxl[(long long)BT * NH * HD];
__device__ float          g_invfreq[128];

// ---------------------------------------------------------------------------
// helpers
// ---------------------------------------------------------------------------
__device__ __forceinline__ uint32_t smem_u32(const void* p) {
    uint32_t a;
    asm("{ .reg .u64 t; cvta.to.shared.u64 t, %1; cvt.u32.u64 %0, t; }"
        : "=r"(a) : "l"(p));
    return a;
}
__device__ __forceinline__ void cp16(uint32_t s, const void* g) {
    asm volatile("cp.async.cg.shared.global [%0], [%1], 16;" :: "r"(s), "l"(g));
}
#define CP_COMMIT() asm volatile("cp.async.commit_group;")
#define CP_WAIT(n)  asm volatile("cp.async.wait_group %0;" :: "n"(n))

__device__ __forceinline__ void ldm_x4(uint32_t* r, uint32_t addr) {
    asm volatile("ldmatrix.sync.aligned.m8n8.x4.shared.b16 {%0,%1,%2,%3}, [%4];"
        : "=r"(r[0]), "=r"(r[1]), "=r"(r[2]), "=r"(r[3]) : "r"(addr));
}
__device__ __forceinline__ void mma_bf16(float* d, const uint32_t* a,
                                         const uint32_t* b) {
    asm volatile(
        "mma.sync.aligned.m16n8k16.row.col.f32.bf16.bf16.f32 "
        "{%0,%1,%2,%3}, {%4,%5,%6,%7}, {%8,%9}, {%0,%1,%2,%3};"
        : "+f"(d[0]), "+f"(d[1]), "+f"(d[2]), "+f"(d[3])
        : "r"(a[0]), "r"(a[1]), "r"(a[2]), "r"(a[3]), "r"(b[0]), "r"(b[1]));
}
__device__ __forceinline__ void split2(float v, __nv_bfloat16& h, __nv_bfloat16& l) {
    h = __float2bfloat16(v);
    l = __float2bfloat16(v - __bfloat162float(h));
}

// ---------------------------------------------------------------------------
// HMMA GEMM:  C[M,N] = A[M,K] @ B[N,K]^T, A/B bf16 hi+lo (K-major), fp32 acc.
// C = Ah*Bh + Ah*Bl + Al*Bh  (Al*Bl dropped: ~2^-18 rel)
// Block 128x128, 8 warps (2Mx4N), warp 64x32, K-chunk 32, double-buffered
// cp.async. SMEM row pitch 80B -> ldmatrix conflict-free (mod-128 distinct).
// Batch z: off = (z/div)*s1 + ((z%div)/g)*s2  (elements)
// outPair=0: fp32 -> Cf ; outPair=1: bf16 hi/lo -> Ch/Cl
// ---------------------------------------------------------------------------
#define GBM 128
#define GBN 128
#define GBK 32
#define PITCH 80
#define TILE_B (128 * PITCH)          // 10240
#define STAGE  (4 * TILE_B)           // 40960
#define GEMM_SMEM (2 * STAGE)         // 81920

__global__ __launch_bounds__(256, 1) void mma_gemm(
    const __nv_bfloat16* __restrict__ Ah, const __nv_bfloat16* __restrict__ Al,
    const __nv_bfloat16* __restrict__ Bh, const __nv_bfloat16* __restrict__ Bl,
    float* __restrict__ Cf, __nv_bfloat16* __restrict__ Ch, __nv_bfloat16* __restrict__ Cl,
    int K, int ldc, int outPair,
    long long aDiv, long long aG, long long aS1, long long aS2,
    long long bDiv, long long bG, long long bS1, long long bS2,
    long long cDiv, long long cG, long long cS1, long long cS2)
{
    extern __shared__ char smem[];
    uint32_t sb = smem_u32(smem);
    int tid = threadIdx.x, wid = tid >> 5, lane = tid & 31;
    int warpM = wid >> 2, warpN = wid & 3;

    long long z = blockIdx.z;
    long long offA = (z / aDiv) * aS1 + ((z % aDiv) / aG) * aS2;
    long long offB = (z / bDiv) * bS1 + ((z % bDiv) / bG) * bS2;
    long long offC = (z / cDiv) * cS1 + ((z % cDiv) / cG) * cS2;

    int brow = blockIdx.y * GBM;
    int bcol = blockIdx.x * GBN;
    long long rowB = (long long)K * 2;

    const char* src[4];
    src[0] = (const char*)(Ah + offA) + (long long)brow * rowB;
    src[1] = (const char*)(Al + offA) + (long long)brow * rowB;
    src[2] = (const char*)(Bh + offB) + (long long)bcol * rowB;
    src[3] = (const char*)(Bl + offB) + (long long)bcol * rowB;

    // loader: 4 tiles x 128 rows x 64B payload, pitch 80
    auto load_chunk = [&](int chunk, int stage) {
        uint32_t st = sb + stage * STAGE;
        long long kb = (long long)chunk * GBK * 2;
        #pragma unroll
        for (int t = 0; t < 8; t++) {
            int tile = t >> 1;
            int within = (t & 1) * 256 + tid;       // 0..511
            int r = within >> 2, c = within & 3;
            cp16(st + tile * TILE_B + r * PITCH + c * 16,
                 src[tile] + (long long)r * rowB + kb + c * 16);
        }
        CP_COMMIT();
    };

    float acc[4][4][4];
    #pragma unroll
    for (int i = 0; i < 4; i++)
        #pragma unroll
        for (int j = 0; j < 4; j++)
            #pragma unroll
            for (int k = 0; k < 4; k++) acc[i][j][k] = 0.0f;

    int nCh = K / GBK;
    load_chunk(0, 0);

    for (int i = 0; i < nCh; i++) {
        if (i + 1 < nCh) { load_chunk(i + 1, (i + 1) & 1); CP_WAIT(1); }
        else             { CP_WAIT(0); }
        __syncthreads();

        uint32_t st = sb + (i & 1) * STAGE;
        uint32_t baseAh = st + warpM * 64 * PITCH;
        uint32_t baseAl = baseAh + TILE_B;
        uint32_t baseBh = st + 2 * TILE_B + warpN * 32 * PITCH;
        uint32_t baseBl = baseBh + TILE_B;

        int aRow = lane & 15;             // row within 16-row group
        int aCol = (lane >> 4) * 16;      // 0 or 16 (k halves of 16B)
        int bRow = (lane >> 4) * 8 + (lane & 7);   // row within 16-n group
        int bCol = ((lane >> 3) & 1) * 16;

        #pragma unroll
        for (int s = 0; s < 2; s++) {     // two k16 steps per 32-chunk
            uint32_t aH[4][4], aL[4][4], bHf[4][2], bLf[4][2];
            #pragma unroll
            for (int mg = 0; mg < 4; mg++) {
                uint32_t off = (mg * 16 + aRow) * PITCH + s * 32 + aCol;
                ldm_x4(aH[mg], baseAh + off);
                ldm_x4(aL[mg], baseAl + off);
            }
            #pragma unroll
            for (int np = 0; np < 2; np++) {
                uint32_t r4[4];
                uint32_t off = (np * 16 + bRow) * PITCH + s * 32 + bCol;
                ldm_x4(r4, baseBh + off);
                bHf[np*2][0] = r4[0]; bHf[np*2][1] = r4[1];
                bHf[np*2+1][0] = r4[2]; bHf[np*2+1][1] = r4[3];
                ldm_x4(r4, baseBl + off);
                bLf[np*2][0] = r4[0]; bLf[np*2][1] = r4[1];
                bLf[np*2+1][0] = r4[2]; bLf[np*2+1][1] = r4[3];
            }
            #pragma unroll
            for (int mg = 0; mg < 4; mg++)
                #pragma unroll
                for (int nt = 0; nt < 4; nt++) {
                    mma_bf16(acc[mg][nt], aH[mg], bHf[nt]);
                    mma_bf16(acc[mg][nt], aH[mg], bLf[nt]);
                    mma_bf16(acc[mg][nt], aL[mg], bHf[nt]);
                }
        }
        __syncthreads();
    }

    // ---- epilogue: direct register -> gmem ----
    #pragma unroll
    for (int mg = 0; mg < 4; mg++) {
        #pragma unroll
        for (int nt = 0; nt < 4; nt++) {
            int r0 = brow + warpM * 64 + mg * 16 + (lane >> 2);
            int c  = bcol + warpN * 32 + nt * 8 + (lane & 3) * 2;
            float* a4 = acc[mg][nt];
            if (!outPair) {
                *(float2*)(Cf + offC + (long long)r0 * ldc + c) =
                    make_float2(a4[0], a4[1]);
                *(float2*)(Cf + offC + (long long)(r0 + 8) * ldc + c) =
                    make_float2(a4[2], a4[3]);
            } else {
                #pragma unroll
                for (int hh = 0; hh < 2; hh++) {
                    __nv_bfloat16 h0, l0, h1, l1;
                    split2(a4[hh * 2 + 0], h0, l0);
                    split2(a4[hh * 2 + 1], h1, l1);
                    uint32_t hw = (uint32_t)*(uint16_t*)&h0 |
                                  ((uint32_t)*(uint16_t*)&h1 << 16);
                    uint32_t lw = (uint32_t)*(uint16_t*)&l0 |
                                  ((uint32_t)*(uint16_t*)&l1 << 16);
                    long long o = offC + (long long)(r0 + hh * 8) * ldc + c;
                    *(uint32_t*)(Ch + o) = hw;
                    *(uint32_t*)(Cl + o) = lw;
                }
            }
        }
    }
}

// ---------------------------------------------------------------------------
// fp32 -> bf16 hi/lo elementwise (for x)
// ---------------------------------------------------------------------------
__global__ void convert_pair_kernel(const float* __restrict__ src,
                                    __nv_bfloat16* __restrict__ dh,
                                    __nv_bfloat16* __restrict__ dl, long long n)
{
    long long i = (long long)(blockIdx.x) * blockDim.x + threadIdx.x;
    long long stride = (long long)gridDim.x * blockDim.x;
    for (; i * 4 < n; i += stride) {
        float4 v = ((const float4*)src)[i];
        __nv_bfloat16 h, l;
        split2(v.x, h, l); dh[i*4+0] = h; dl[i*4+0] = l;
        split2(v.y, h, l); dh[i*4+1] = h; dl[i*4+1] = l;
        split2(v.z, h, l); dh[i*4+2] = h; dl[i*4+2] = l;
        split2(v.w, h, l); dh[i*4+3] = h; dl[i*4+3] = l;
    }
}

// ---------------------------------------------------------------------------
// Transpose + convert: src fp32 [R,C] (row stride lds) -> dst bf16 pair [C,R]
// (row stride ldd).  Per-z: srcOff = (z/div)*s1 + (z%div)*s2 + add; dst z*dstZ.
// ---------------------------------------------------------------------------
__global__ void transpose_convert_kernel(
    const float* __restrict__ src, __nv_bfloat16* __restrict__ dh,
    __nv_bfloat16* __restrict__ dl, int lds, int ldd,
    long long sDiv, long long sS1, long long sS2, long long sAdd, long long dstZ)
{
    __shared__ float tile[32][33];
    long long z = blockIdx.z;
    const float* s = src + (z / sDiv) * sS1 + (z % sDiv) * sS2 + sAdd;
    long long doff = z * dstZ;

    int tx = threadIdx.x, ty = threadIdx.y;
    int c0 = blockIdx.x * 32, r0 = blockIdx.y * 32;
    #pragma unroll
    for (int i = 0; i < 4; i++) {
        int r = r0 + ty + i * 8;
        tile[ty + i * 8][tx] = s[(long long)r * lds + c0 + tx];
    }
    __syncthreads();
    #pragma unroll
    for (int i = 0; i < 4; i++) {
        int dr = c0 + ty + i * 8;
        int dc = r0 + tx;
        float v = tile[tx][ty + i * 8];
        __nv_bfloat16 h, l;
        split2(v, h, l);
        dh[doff + (long long)dr * ldd + dc] = h;
        dl[doff + (long long)dr * ldd + dc] = l;
    }
}

// ---------------------------------------------------------------------------
__global__ void init_invfreq_kernel() {
    int j = threadIdx.x;
    g_invfreq[j] = (float)pow(10000.0, -(double)j / 128.0);
}

// ---------------------------------------------------------------------------
// RMSNorm + RoPE + split-convert + cache scatter.
// grid (BT, 16): y 0..7 Q heads, 8..11 K heads, 12..15 V cache copy.
// ---------------------------------------------------------------------------
__device__ __forceinline__ float block_sum_128(float v) {
    #pragma unroll
    for (int o = 16; o > 0; o >>= 1) v += __shfl_xor_sync(0xffffffffu, v, o);
    __shared__ float sh[4];
    int w = threadIdx.x >> 5;
    if ((threadIdx.x & 31) == 0) sh[w] = v;
    __syncthreads();
    return sh[0] + sh[1] + sh[2] + sh[3];
}

__global__ void normrope_kernel(
    const float* __restrict__ qw, const float* __restrict__ kw,
    const int* __restrict__ posp, const int* __restrict__ cip,
    float* __restrict__ outk, float* __restrict__ outv)
{
    int bt  = blockIdx.x;
    int b   = bt / TT, t = bt - b * TT;
    int hsl = blockIdx.y;
    int tid = threadIdx.x;

    if (hsl >= NH + NKV) {                 // V: cache copy only
        int h = hsl - NH - NKV;
        int ci = *cip;
        const float* src = g_qkv + (long long)bt * QKVN + 3072 + h * HD;
        float* dc = outv + (((long long)b * NKV + h) * SSZ + ci + t) * HD;
        dc[tid] = src[tid]; dc[tid + 128] = src[tid + 128];
        return;
    }

    bool isQ = (hsl < NH);
    int  h   = isQ ? hsl : hsl - NH;
    int  col = isQ ? h * HD : 2048 + h * HD;
    const float* src = g_qkv + (long long)bt * QKVN + col;
    const float* w = isQ ? qw : kw;

    float v1 = src[tid], v2 = src[tid + 128];
    float ss = block_sum_128(v1 * v1 + v2 * v2);
    float r  = rsqrtf(ss * (1.0f / HD) + 1e-6f);
    float x1 = v1 * r * (1.0f + w[tid]);
    float x2 = v2 * r * (1.0f + w[tid + 128]);

    int pos = *posp + t;
    float ang = (float)pos * g_invfreq[tid];
    double da  = (double)ang;
    double red = da - floor(da * 0.159154943091895335768883763373) *
                      6.283185307179586476925286766559;
    float c = cosf((float)red), s = sinf((float)red);

    float o1 = x1 * c - x2 * s;
    float o2 = x2 * c + x1 * s;

    __nv_bfloat16 h1, l1, h2, l2;
    if (isQ) {
        o1 *= ATT_SCALE; o2 *= ATT_SCALE;
        split2(o1, h1, l1); split2(o2, h2, l2);
        long long base = (((long long)b * NH + h) * TT + t) * HD;
        g_qph[base + tid] = h1;       g_qpl[base + tid] = l1;
        g_qph[base + tid + 128] = h2; g_qpl[base + tid + 128] = l2;
    } else {
        split2(o1, h1, l1); split2(o2, h2, l2);
        long long base = (((long long)b * NKV + h) * TT + t) * HD;
        g_kph[base + tid] = h1;       g_kpl[base + tid] = l1;
        g_kph[base + tid + 128] = h2; g_kpl[base + tid + 128] = l2;
        int ci = *cip;
        float* dc = outk + (((long long)b * NKV + h) * SSZ + ci + t) * HD;
        dc[tid] = o1; dc[tid + 128] = o2;
    }
}

// ---------------------------------------------------------------------------
// Row softmax over 1024 keys, writes P as bf16 hi/lo pairs.
// ---------------------------------------------------------------------------
__global__ __launch_bounds__(256) void softmax_kernel()
{
    long long row = blockIdx.x;
    const float* p = g_sc + row * TT;
    int tid = threadIdx.x;

    float4 v = ((const float4*)p)[tid];
    float m = fmaxf(fmaxf(v.x, v.y), fmaxf(v.z, v.w));
    #pragma unroll
    for (int o = 16; o > 0; o >>= 1) m = fmaxf(m, __shfl_xor_sync(0xffffffffu, m, o));
    __shared__ float sm[8];
    int w = tid >> 5;
    if ((tid & 31) == 0) sm[w] = m;
    __syncthreads();
    m = fmaxf(fmaxf(fmaxf(sm[0], sm[1]), fmaxf(sm[2], sm[3])),
              fmaxf(fmaxf(sm[4], sm[5]), fmaxf(sm[6], sm[7])));

    float e0 = expf(v.x - m), e1 = expf(v.y - m), e2 = expf(v.z - m), e3 = expf(v.w - m);
    float sum = e0 + e1 + e2 + e3;
    #pragma unroll
    for (int o = 16; o > 0; o >>= 1) sum += __shfl_xor_sync(0xffffffffu, sum, o);
    __shared__ float s2[8];
    if ((tid & 31) == 0) s2[w] = sum;
    __syncthreads();
    sum = s2[0] + s2[1] + s2[2] + s2[3] + s2[4] + s2[5] + s2[6] + s2[7];

    float inv = 1.0f / sum;
    float pv[4] = {e0 * inv, e1 * inv, e2 * inv, e3 * inv};
    uint32_t hw[2], lw[2];
    #pragma unroll
    for (int j = 0; j < 2; j++) {
        __nv_bfloat16 h0, l0, h1, l1;
        split2(pv[2 * j], h0, l0);
        split2(pv[2 * j + 1], h1, l1);
        hw[j] = (uint32_t)*(uint16_t*)&h0 | ((uint32_t)*(uint16_t*)&h1 << 16);
        lw[j] = (uint32_t)*(uint16_t*)&l0 | ((uint32_t)*(uint16_t*)&l1 << 16);
    }
    long long o = row * TT + tid * 4;
    *(uint2*)(g_ph + o) = make_uint2(hw[0], hw[1]);
    *(uint2*)(g_pl + o) = make_uint2(lw[0], lw[1]);
}

// ---------------------------------------------------------------------------
// kernel_launch
// ---------------------------------------------------------------------------
extern "C" void kernel_launch(void* const* d_in, const int* in_sizes, int n_in,
                              void* d_out, int out_size)
{
    const float* x       = (const float*)d_in[0];
    const float* k_cache = (const float*)d_in[1];
    const float* v_cache = (const float*)d_in[2];
    const float* wq      = (const float*)d_in[3];
    const float* wk      = (const float*)d_in[4];
    const float* wv      = (const float*)d_in[5];
    const float* wo      = (const float*)d_in[6];
    const float* qw      = (const float*)d_in[7];
    const float* kw      = (const float*)d_in[8];
    const int*   posp    = (const int*)d_in[9];
    const int*   cip     = (const int*)d_in[10];

    float* out  = (float*)d_out;
    float* outk = out  + (long long)BB * TT * HID;
    float* outv = outk + (long long)BB * NKV * SSZ * HD;

    float *pqkv, *psc;
    __nv_bfloat16 *pxh, *pxl, *pwth, *pwtl, *pwoth, *pwotl;
    __nv_bfloat16 *pqph, *pqpl, *pkph, *pkpl, *pvth, *pvtl, *pph, *ppl, *pcth, *pctl;
    cudaGetSymbolAddress((void**)&pqkv,  g_qkv);
    cudaGetSymbolAddress((void**)&psc,   g_sc);
    cudaGetSymbolAddress((void**)&pxh,   g_xh);
    cudaGetSymbolAddress((void**)&pxl,   g_xl);
    cudaGetSymbolAddress((void**)&pwth,  g_wth);
    cudaGetSymbolAddress((void**)&pwtl,  g_wtl);
    cudaGetSymbolAddress((void**)&pwoth, g_woth);
    cudaGetSymbolAddress((void**)&pwotl, g_wotl);
    cudaGetSymbolAddress((void**)&pqph,  g_qph);
    cudaGetSymbolAddress((void**)&pqpl,  g_qpl);
    cudaGetSymbolAddress((void**)&pkph,  g_kph);
    cudaGetSymbolAddress((void**)&pkpl,  g_kpl);
    cudaGetSymbolAddress((void**)&pvth,  g_vth);
    cudaGetSymbolAddress((void**)&pvtl,  g_vtl);
    cudaGetSymbolAddress((void**)&pph,   g_ph);
    cudaGetSymbolAddress((void**)&ppl,   g_pl);
    cudaGetSymbolAddress((void**)&pcth,  g_ctxh);
    cudaGetSymbolAddress((void**)&pctl,  g_ctxl);

    cudaFuncSetAttribute(mma_gemm, cudaFuncAttributeMaxDynamicSharedMemorySize, GEMM_SMEM);

    // cache copies (new slice overwritten later in-stream)
    size_t cacheBytes = sizeof(float) * (size_t)BB * NKV * SSZ * HD;
    cudaMemcpyAsync(outk, k_cache, cacheBytes, cudaMemcpyDeviceToDevice, 0);
    cudaMemcpyAsync(outv, v_cache, cacheBytes, cudaMemcpyDeviceToDevice, 0);

    init_invfreq_kernel<<<1, 128>>>();

    const long long BIG = 1LL << 30;
    dim3 tb(32, 8);

    // x -> bf16 pair
    convert_pair_kernel<<<512, 256>>>(x, pxh, pxl, (long long)BT * HID);

    // weights -> transposed bf16 pairs
    transpose_convert_kernel<<<dim3(2048/32, HID/32, 1), tb>>>(
        wq, pwth, pwtl, 2048, HID, 1, 0, 0, 0, 0);
    transpose_convert_kernel<<<dim3(1024/32, HID/32, 1), tb>>>(
        wk, pwth + 2048LL*HID, pwtl + 2048LL*HID, 1024, HID, 1, 0, 0, 0, 0);
    transpose_convert_kernel<<<dim3(1024/32, HID/32, 1), tb>>>(
        wv, pwth + 3072LL*HID, pwtl + 3072LL*HID, 1024, HID, 1, 0, 0, 0, 0);
    transpose_convert_kernel<<<dim3(HID/32, 2048/32, 1), tb>>>(
        wo, pwoth, pwotl, HID, 2048, 1, 0, 0, 0, 0);

    // QKV projection: [2048,4096] fp32
    mma_gemm<<<dim3(QKVN/GBN, BT/GBM, 1), 256, GEMM_SMEM>>>(
        pxh, pxl, pwth, pwtl, pqkv, nullptr, nullptr, HID, QKVN, 0,
        BIG,1,0,0,  BIG,1,0,0,  BIG,1,0,0);

    // norm + rope + splits + cache scatter
    normrope_kernel<<<dim3(BT, 16), 128>>>(qw, kw, posp, cip, outk, outv);

    // V^T bf16 pairs: per z=(b,kv): src [1024,256] in g_qkv -> [256,1024]
    transpose_convert_kernel<<<dim3(HD/32, TT/32, BB*NKV), tb>>>(
        pqkv, pvth, pvtl, QKVN, TT,
        NKV, (long long)TT*QKVN, HD, 3072, (long long)HD*TT);

    // scores: z=(b,h): Q[1024,256] @ K[1024,256]^T -> fp32 [1024,1024]
    mma_gemm<<<dim3(TT/GBN, TT/GBM, BB*NH), 256, GEMM_SMEM>>>(
        pqph, pqpl, pkph, pkpl, psc, nullptr, nullptr, HD, TT, 0,
        BIG,1,0,(long long)TT*HD,
        NH,2,(long long)NKV*TT*HD,(long long)TT*HD,
        BIG,1,0,(long long)TT*TT);

    // softmax -> P pairs
    softmax_kernel<<<(long long)BB*NH*TT, 256>>>();

    // PV: z=(b,h): P[1024,1024] @ V^T[256,1024]^T -> ctx pairs [bt, h*256+d]
    mma_gemm<<<dim3(HD/GBN, TT/GBM, BB*NH), 256, GEMM_SMEM>>>(
        pph, ppl, pvth, pvtl, nullptr, pcth, pctl, TT, NH*HD, 1,
        BIG,1,0,(long long)TT*TT,
        NH,2,(long long)NKV*HD*TT,(long long)HD*TT,
        NH,1,(long long)TT*NH*HD,(long long)HD);

    // out projection: ctx [2048,2048] @ wo^T -> out fp32 [2048,2560]
    mma_gemm<<<dim3(HID/GBN, BT/GBM, 1), 256, GEMM_SMEM>>>(
        pcth, pctl, pwoth, pwotl, out, nullptr, nullptr, NH*HD, HID, 0,
        BIG,1,0,0,  BIG,1,0,0,  BIG,1,0,0);
}

// round 7
// speedup vs baseline: 3.0165x; 1.0036x over previous
#include <cuda_runtime.h>
#include <cuda_bf16.h>
#include <cstdint>
#include <math.h>

// ---------------------------------------------------------------------------
// Gemma3Attention on GB300 (compute_103 target -> no tcgen05; use mma.sync
// HMMA bf16 with hi/lo split, fp32 accumulate).
// B=2, T=1024, S=4096, HIDDEN=2560, HEADS=8, KV_HEADS=4, HEAD_DIM=256.
// valid keys == [cache_index, cache_index+T) exactly -> attention only over
// the freshly projected K/V tokens.
// GEMM config: NSTAGE=2 / 80KB SMEM (the proven-passing Round-4 config).
// ---------------------------------------------------------------------------
#define BB   2
#define TT   1024
#define SSZ  4096
#define HID  2560
#define NH   8
#define NKV  4
#define HD   256
#define BT   (BB * TT)            // 2048
#define QKVN 4096                 // 2048 q + 1024 k + 1024 v cols
#define ATT_SCALE 0.0625f

// ---------------- scratch (device globals) ---------------------------------
__device__ float          g_qkv [(long long)BT * QKVN];        // fp32 qkv proj
__device__ __nv_bfloat16  g_xh  [(long long)BT * HID];
__device__ __nv_bfloat16  g_xl  [(long long)BT * HID];
__device__ __nv_bfloat16  g_wth [(long long)QKVN * HID];       // [wq;wk;wv]^T
__device__ __nv_bfloat16  g_wtl [(long long)QKVN * HID];
__device__ __nv_bfloat16  g_woth[(long long)HID * (NH * HD)];  // wo^T
__device__ __nv_bfloat16  g_wotl[(long long)HID * (NH * HD)];
__device__ __nv_bfloat16  g_qph [(long long)BB * NH  * TT * HD];
__device__ __nv_bfloat16  g_qpl [(long long)BB * NH  * TT * HD];
__device__ __nv_bfloat16  g_kph [(long long)BB * NKV * TT * HD];
__device__ __nv_bfloat16  g_kpl [(long long)BB * NKV * TT * HD];
__device__ __nv_bfloat16  g_vth [(long long)BB * NKV * HD * TT];  // V^T
__device__ __nv_bfloat16  g_vtl [(long long)BB * NKV * HD * TT];
__device__ float          g_sc  [(long long)BB * NH * TT * TT];
__device__ __nv_bfloat16  g_ph  [(long long)BB * NH * TT * TT];
__device__ __nv_bfloat16  g_pl  [(long long)BB * NH * TT * TT];
__device__ __nv_bfloat16  g_ctxh[(long long)BT * NH * HD];
__device__ __nv_bfloat16  g_ctxl[(long long)BT * NH * HD];
__device__ float          g_invfreq[128];

// ---------------------------------------------------------------------------
// helpers
// ---------------------------------------------------------------------------
__device__ __forceinline__ uint32_t smem_u32(const void* p) {
    uint32_t a;
    asm("{ .reg .u64 t; cvta.to.shared.u64 t, %1; cvt.u32.u64 %0, t; }"
        : "=r"(a) : "l"(p));
    return a;
}
__device__ __forceinline__ void cp16(uint32_t s, const void* g) {
    asm volatile("cp.async.cg.shared.global [%0], [%1], 16;" :: "r"(s), "l"(g));
}
#define CP_COMMIT() asm volatile("cp.async.commit_group;")
#define CP_WAIT(n)  asm volatile("cp.async.wait_group %0;" :: "n"(n))

__device__ __forceinline__ void ldm_x4(uint32_t* r, uint32_t addr) {
    asm volatile("ldmatrix.sync.aligned.m8n8.x4.shared.b16 {%0,%1,%2,%3}, [%4];"
        : "=r"(r[0]), "=r"(r[1]), "=r"(r[2]), "=r"(r[3]) : "r"(addr));
}
__device__ __forceinline__ void mma_bf16(float* d, const uint32_t* a,
                                         const uint32_t* b) {
    asm volatile(
        "mma.sync.aligned.m16n8k16.row.col.f32.bf16.bf16.f32 "
        "{%0,%1,%2,%3}, {%4,%5,%6,%7}, {%8,%9}, {%0,%1,%2,%3};"
        : "+f"(d[0]), "+f"(d[1]), "+f"(d[2]), "+f"(d[3])
        : "r"(a[0]), "r"(a[1]), "r"(a[2]), "r"(a[3]), "r"(b[0]), "r"(b[1]));
}
__device__ __forceinline__ void split2(float v, __nv_bfloat16& h, __nv_bfloat16& l) {
    h = __float2bfloat16(v);
    l = __float2bfloat16(v - __bfloat162float(h));
}

// ---------------------------------------------------------------------------
// HMMA GEMM:  C[M,N] = A[M,K] @ B[N,K]^T, A/B bf16 hi+lo (K-major), fp32 acc.
// C = Ah*Bh + Ah*Bl + Al*Bh  (Al*Bl dropped: ~2^-18 rel)
// Block 128x128, 8 warps (2Mx4N), warp 64x32, K-chunk 32, double-buffered
// cp.async (NSTAGE=2, 80KB -- the proven config). SMEM row pitch 80B ->
// ldmatrix conflict-free (mod-128 distinct).
// Batch z: off = (z/div)*s1 + ((z%div)/g)*s2  (elements)
// outPair=0: fp32 -> Cf ; outPair=1: bf16 hi/lo -> Ch/Cl
// ---------------------------------------------------------------------------
#define GBM 128
#define GBN 128
#define GBK 32
#define PITCH 80
#define TILE_B (128 * PITCH)          // 10240
#define STAGE  (4 * TILE_B)           // 40960
#define GEMM_SMEM (2 * STAGE)         // 81920

__global__ __launch_bounds__(256, 1) void mma_gemm(
    const __nv_bfloat16* __restrict__ Ah, const __nv_bfloat16* __restrict__ Al,
    const __nv_bfloat16* __restrict__ Bh, const __nv_bfloat16* __restrict__ Bl,
    float* __restrict__ Cf, __nv_bfloat16* __restrict__ Ch, __nv_bfloat16* __restrict__ Cl,
    int K, int ldc, int outPair,
    long long aDiv, long long aG, long long aS1, long long aS2,
    long long bDiv, long long bG, long long bS1, long long bS2,
    long long cDiv, long long cG, long long cS1, long long cS2)
{
    extern __shared__ char smem[];
    uint32_t sb = smem_u32(smem);
    int tid = threadIdx.x, wid = tid >> 5, lane = tid & 31;
    int warpM = wid >> 2, warpN = wid & 3;

    long long z = blockIdx.z;
    long long offA = (z / aDiv) * aS1 + ((z % aDiv) / aG) * aS2;
    long long offB = (z / bDiv) * bS1 + ((z % bDiv) / bG) * bS2;
    long long offC = (z / cDiv) * cS1 + ((z % cDiv) / cG) * cS2;

    int brow = blockIdx.y * GBM;
    int bcol = blockIdx.x * GBN;
    long long rowB = (long long)K * 2;

    const char* src[4];
    src[0] = (const char*)(Ah + offA) + (long long)brow * rowB;
    src[1] = (const char*)(Al + offA) + (long long)brow * rowB;
    src[2] = (const char*)(Bh + offB) + (long long)bcol * rowB;
    src[3] = (const char*)(Bl + offB) + (long long)bcol * rowB;

    // loader: 4 tiles x 128 rows x 64B payload, pitch 80; one commit group.
    auto load_chunk = [&](int chunk, int stage) {
        uint32_t st = sb + stage * STAGE;
        long long kb = (long long)chunk * GBK * 2;
        #pragma unroll
        for (int t = 0; t < 8; t++) {
            int tile = t >> 1;
            int within = (t & 1) * 256 + tid;       // 0..511
            int r = within >> 2, c = within & 3;
            cp16(st + tile * TILE_B + r * PITCH + c * 16,
                 src[tile] + (long long)r * rowB + kb + c * 16);
        }
        CP_COMMIT();
    };

    float acc[4][4][4];
    #pragma unroll
    for (int i = 0; i < 4; i++)
        #pragma unroll
        for (int j = 0; j < 4; j++)
            #pragma unroll
            for (int k = 0; k < 4; k++) acc[i][j][k] = 0.0f;

    int nCh = K / GBK;
    load_chunk(0, 0);

    for (int i = 0; i < nCh; i++) {
        if (i + 1 < nCh) { load_chunk(i + 1, (i + 1) & 1); CP_WAIT(1); }
        else             { CP_WAIT(0); }
        __syncthreads();

        uint32_t st = sb + (i & 1) * STAGE;
        uint32_t baseAh = st + warpM * 64 * PITCH;
        uint32_t baseAl = baseAh + TILE_B;
        uint32_t baseBh = st + 2 * TILE_B + warpN * 32 * PITCH;
        uint32_t baseBl = baseBh + TILE_B;

        int aRow = lane & 15;
        int aCol = (lane >> 4) * 16;
        int bRow = (lane >> 4) * 8 + (lane & 7);
        int bCol = ((lane >> 3) & 1) * 16;

        #pragma unroll
        for (int s = 0; s < 2; s++) {     // two k16 steps per 32-chunk
            uint32_t aH[4][4], aL[4][4], bHf[4][2], bLf[4][2];
            #pragma unroll
            for (int mg = 0; mg < 4; mg++) {
                uint32_t off = (mg * 16 + aRow) * PITCH + s * 32 + aCol;
                ldm_x4(aH[mg], baseAh + off);
                ldm_x4(aL[mg], baseAl + off);
            }
            #pragma unroll
            for (int np = 0; np < 2; np++) {
                uint32_t r4[4];
                uint32_t off = (np * 16 + bRow) * PITCH + s * 32 + bCol;
                ldm_x4(r4, baseBh + off);
                bHf[np*2][0] = r4[0]; bHf[np*2][1] = r4[1];
                bHf[np*2+1][0] = r4[2]; bHf[np*2+1][1] = r4[3];
                ldm_x4(r4, baseBl + off);
                bLf[np*2][0] = r4[0]; bLf[np*2][1] = r4[1];
                bLf[np*2+1][0] = r4[2]; bLf[np*2+1][1] = r4[3];
            }
            #pragma unroll
            for (int mg = 0; mg < 4; mg++)
                #pragma unroll
                for (int nt = 0; nt < 4; nt++) {
                    mma_bf16(acc[mg][nt], aH[mg], bHf[nt]);
                    mma_bf16(acc[mg][nt], aH[mg], bLf[nt]);
                    mma_bf16(acc[mg][nt], aL[mg], bHf[nt]);
                }
        }
        __syncthreads();
    }

    // ---- epilogue: direct register -> gmem ----
    #pragma unroll
    for (int mg = 0; mg < 4; mg++) {
        #pragma unroll
        for (int nt = 0; nt < 4; nt++) {
            int r0 = brow + warpM * 64 + mg * 16 + (lane >> 2);
            int c  = bcol + warpN * 32 + nt * 8 + (lane & 3) * 2;
            float* a4 = acc[mg][nt];
            if (!outPair) {
                *(float2*)(Cf + offC + (long long)r0 * ldc + c) =
                    make_float2(a4[0], a4[1]);
                *(float2*)(Cf + offC + (long long)(r0 + 8) * ldc + c) =
                    make_float2(a4[2], a4[3]);
            } else {
                #pragma unroll
                for (int hh = 0; hh < 2; hh++) {
                    __nv_bfloat16 h0, l0, h1, l1;
                    split2(a4[hh * 2 + 0], h0, l0);
                    split2(a4[hh * 2 + 1], h1, l1);
                    uint32_t hw = (uint32_t)*(uint16_t*)&h0 |
                                  ((uint32_t)*(uint16_t*)&h1 << 16);
                    uint32_t lw = (uint32_t)*(uint16_t*)&l0 |
                                  ((uint32_t)*(uint16_t*)&l1 << 16);
                    long long o = offC + (long long)(r0 + hh * 8) * ldc + c;
                    *(uint32_t*)(Ch + o) = hw;
                    *(uint32_t*)(Cl + o) = lw;
                }
            }
        }
    }
}

// ---------------------------------------------------------------------------
// fp32 -> bf16 hi/lo elementwise (for x)
// ---------------------------------------------------------------------------
__global__ void convert_pair_kernel(const float* __restrict__ src,
                                    __nv_bfloat16* __restrict__ dh,
                                    __nv_bfloat16* __restrict__ dl, long long n)
{
    long long i = (long long)(blockIdx.x) * blockDim.x + threadIdx.x;
    long long stride = (long long)gridDim.x * blockDim.x;
    for (; i * 4 < n; i += stride) {
        float4 v = ((const float4*)src)[i];
        __nv_bfloat16 h, l;
        split2(v.x, h, l); dh[i*4+0] = h; dl[i*4+0] = l;
        split2(v.y, h, l); dh[i*4+1] = h; dl[i*4+1] = l;
        split2(v.z, h, l); dh[i*4+2] = h; dl[i*4+2] = l;
        split2(v.w, h, l); dh[i*4+3] = h; dl[i*4+3] = l;
    }
}

// ---------------------------------------------------------------------------
// Transpose + convert: src fp32 [R,C] (row stride lds) -> dst bf16 pair [C,R]
// (row stride ldd).  Per-z: srcOff = (z/div)*s1 + (z%div)*s2 + add; dst z*dstZ.
// ---------------------------------------------------------------------------
__global__ void transpose_convert_kernel(
    const float* __restrict__ src, __nv_bfloat16* __restrict__ dh,
    __nv_bfloat16* __restrict__ dl, int lds, int ldd,
    long long sDiv, long long sS1, long long sS2, long long sAdd, long long dstZ)
{
    __shared__ float tile[32][33];
    long long z = blockIdx.z;
    const float* s = src + (z / sDiv) * sS1 + (z % sDiv) * sS2 + sAdd;
    long long doff = z * dstZ;

    int tx = threadIdx.x, ty = threadIdx.y;
    int c0 = blockIdx.x * 32, r0 = blockIdx.y * 32;
    #pragma unroll
    for (int i = 0; i < 4; i++) {
        int r = r0 + ty + i * 8;
        tile[ty + i * 8][tx] = s[(long long)r * lds + c0 + tx];
    }
    __syncthreads();
    #pragma unroll
    for (int i = 0; i < 4; i++) {
        int dr = c0 + ty + i * 8;
        int dc = r0 + tx;
        float v = tile[tx][ty + i * 8];
        __nv_bfloat16 h, l;
        split2(v, h, l);
        dh[doff + (long long)dr * ldd + dc] = h;
        dl[doff + (long long)dr * ldd + dc] = l;
    }
}

// ---------------------------------------------------------------------------
__global__ void init_invfreq_kernel() {
    int j = threadIdx.x;
    g_invfreq[j] = (float)pow(10000.0, -(double)j / 128.0);
}

// ---------------------------------------------------------------------------
// RMSNorm + RoPE + split-convert + cache scatter.
// grid (BT, 16): y 0..7 Q heads, 8..11 K heads, 12..15 V cache copy.
// ---------------------------------------------------------------------------
__device__ __forceinline__ float block_sum_128(float v) {
    #pragma unroll
    for (int o = 16; o > 0; o >>= 1) v += __shfl_xor_sync(0xffffffffu, v, o);
    __shared__ float sh[4];
    int w = threadIdx.x >> 5;
    if ((threadIdx.x & 31) == 0) sh[w] = v;
    __syncthreads();
    return sh[0] + sh[1] + sh[2] + sh[3];
}

__global__ void normrope_kernel(
    const float* __restrict__ qw, const float* __restrict__ kw,
    const int* __restrict__ posp, const int* __restrict__ cip,
    float* __restrict__ outk, float* __restrict__ outv)
{
    int bt  = blockIdx.x;
    int b   = bt / TT, t = bt - b * TT;
    int hsl = blockIdx.y;
    int tid = threadIdx.x;

    if (hsl >= NH + NKV) {                 // V: cache copy only
        int h = hsl - NH - NKV;
        int ci = *cip;
        const float* src = g_qkv + (long long)bt * QKVN + 3072 + h * HD;
        float* dc = outv + (((long long)b * NKV + h) * SSZ + ci + t) * HD;
        dc[tid] = src[tid]; dc[tid + 128] = src[tid + 128];
        return;
    }

    bool isQ = (hsl < NH);
    int  h   = isQ ? hsl : hsl - NH;
    int  col = isQ ? h * HD : 2048 + h * HD;
    const float* src = g_qkv + (long long)bt * QKVN + col;
    const float* w = isQ ? qw : kw;

    float v1 = src[tid], v2 = src[tid + 128];
    float ss = block_sum_128(v1 * v1 + v2 * v2);
    float r  = rsqrtf(ss * (1.0f / HD) + 1e-6f);
    float x1 = v1 * r * (1.0f + w[tid]);
    float x2 = v2 * r * (1.0f + w[tid + 128]);

    int pos = *posp + t;
    float ang = (float)pos * g_invfreq[tid];
    double da  = (double)ang;
    double red = da - floor(da * 0.159154943091895335768883763373) *
                      6.283185307179586476925286766559;
    float c = cosf((float)red), s = sinf((float)red);

    float o1 = x1 * c - x2 * s;
    float o2 = x2 * c + x1 * s;

    __nv_bfloat16 h1, l1, h2, l2;
    if (isQ) {
        o1 *= ATT_SCALE; o2 *= ATT_SCALE;
        split2(o1, h1, l1); split2(o2, h2, l2);
        long long base = (((long long)b * NH + h) * TT + t) * HD;
        g_qph[base + tid] = h1;       g_qpl[base + tid] = l1;
        g_qph[base + tid + 128] = h2; g_qpl[base + tid + 128] = l2;
    } else {
        split2(o1, h1, l1); split2(o2, h2, l2);
        long long base = (((long long)b * NKV + h) * TT + t) * HD;
        g_kph[base + tid] = h1;       g_kpl[base + tid] = l1;
        g_kph[base + tid + 128] = h2; g_kpl[base + tid + 128] = l2;
        int ci = *cip;
        float* dc = outk + (((long long)b * NKV + h) * SSZ + ci + t) * HD;
        dc[tid] = o1; dc[tid + 128] = o2;
    }
}

// ---------------------------------------------------------------------------
// Row softmax over 1024 keys, writes P as bf16 hi/lo pairs.
// ---------------------------------------------------------------------------
__global__ __launch_bounds__(256) void softmax_kernel()
{
    long long row = blockIdx.x;
    const float* p = g_sc + row * TT;
    int tid = threadIdx.x;

    float4 v = ((const float4*)p)[tid];
    float m = fmaxf(fmaxf(v.x, v.y), fmaxf(v.z, v.w));
    #pragma unroll
    for (int o = 16; o > 0; o >>= 1) m = fmaxf(m, __shfl_xor_sync(0xffffffffu, m, o));
    __shared__ float sm[8];
    int w = tid >> 5;
    if ((tid & 31) == 0) sm[w] = m;
    __syncthreads();
    m = fmaxf(fmaxf(fmaxf(sm[0], sm[1]), fmaxf(sm[2], sm[3])),
              fmaxf(fmaxf(sm[4], sm[5]), fmaxf(sm[6], sm[7])));

    float e0 = expf(v.x - m), e1 = expf(v.y - m), e2 = expf(v.z - m), e3 = expf(v.w - m);
    float sum = e0 + e1 + e2 + e3;
    #pragma unroll
    for (int o = 16; o > 0; o >>= 1) sum += __shfl_xor_sync(0xffffffffu, sum, o);
    __shared__ float s2[8];
    if ((tid & 31) == 0) s2[w] = sum;
    __syncthreads();
    sum = s2[0] + s2[1] + s2[2] + s2[3] + s2[4] + s2[5] + s2[6] + s2[7];

    float inv = 1.0f / sum;
    float pv[4] = {e0 * inv, e1 * inv, e2 * inv, e3 * inv};
    uint32_t hw[2], lw[2];
    #pragma unroll
    for (int j = 0; j < 2; j++) {
        __nv_bfloat16 h0, l0, h1, l1;
        split2(pv[2 * j], h0, l0);
        split2(pv[2 * j + 1], h1, l1);
        hw[j] = (uint32_t)*(uint16_t*)&h0 | ((uint32_t)*(uint16_t*)&h1 << 16);
        lw[j] = (uint32_t)*(uint16_t*)&l0 | ((uint32_t)*(uint16_t*)&l1 << 16);
    }
    long long o = row * TT + tid * 4;
    *(uint2*)(g_ph + o) = make_uint2(hw[0], hw[1]);
    *(uint2*)(g_pl + o) = make_uint2(lw[0], lw[1]);
}

// ---------------------------------------------------------------------------
// kernel_launch
// Launch order: init, convert, t(wq), t(wk), t(wv), mma_gemm(QKV) -> the 6th
// launch is the big GEMM so ncu (-s 5 -c 1) captures it.
// ---------------------------------------------------------------------------
extern "C" void kernel_launch(void* const* d_in, const int* in_sizes, int n_in,
                              void* d_out, int out_size)
{
    const float* x       = (const float*)d_in[0];
    const float* k_cache = (const float*)d_in[1];
    const float* v_cache = (const float*)d_in[2];
    const float* wq      = (const float*)d_in[3];
    const float* wk      = (const float*)d_in[4];
    const float* wv      = (const float*)d_in[5];
    const float* wo      = (const float*)d_in[6];
    const float* qw      = (const float*)d_in[7];
    const float* kw      = (const float*)d_in[8];
    const int*   posp    = (const int*)d_in[9];
    const int*   cip     = (const int*)d_in[10];

    float* out  = (float*)d_out;
    float* outk = out  + (long long)BB * TT * HID;
    float* outv = outk + (long long)BB * NKV * SSZ * HD;

    float *pqkv, *psc;
    __nv_bfloat16 *pxh, *pxl, *pwth, *pwtl, *pwoth, *pwotl;
    __nv_bfloat16 *pqph, *pqpl, *pkph, *pkpl, *pvth, *pvtl, *pph, *ppl, *pcth, *pctl;
    cudaGetSymbolAddress((void**)&pqkv,  g_qkv);
    cudaGetSymbolAddress((void**)&psc,   g_sc);
    cudaGetSymbolAddress((void**)&pxh,   g_xh);
    cudaGetSymbolAddress((void**)&pxl,   g_xl);
    cudaGetSymbolAddress((void**)&pwth,  g_wth);
    cudaGetSymbolAddress((void**)&pwtl,  g_wtl);
    cudaGetSymbolAddress((void**)&pwoth, g_woth);
    cudaGetSymbolAddress((void**)&pwotl, g_wotl);
    cudaGetSymbolAddress((void**)&pqph,  g_qph);
    cudaGetSymbolAddress((void**)&pqpl,  g_qpl);
    cudaGetSymbolAddress((void**)&pkph,  g_kph);
    cudaGetSymbolAddress((void**)&pkpl,  g_kpl);
    cudaGetSymbolAddress((void**)&pvth,  g_vth);
    cudaGetSymbolAddress((void**)&pvtl,  g_vtl);
    cudaGetSymbolAddress((void**)&pph,   g_ph);
    cudaGetSymbolAddress((void**)&ppl,   g_pl);
    cudaGetSymbolAddress((void**)&pcth,  g_ctxh);
    cudaGetSymbolAddress((void**)&pctl,  g_ctxl);

    cudaFuncSetAttribute(mma_gemm, cudaFuncAttributeMaxDynamicSharedMemorySize, GEMM_SMEM);

    // cache copies (new slice overwritten later in-stream)
    size_t cacheBytes = sizeof(float) * (size_t)BB * NKV * SSZ * HD;
    cudaMemcpyAsync(outk, k_cache, cacheBytes, cudaMemcpyDeviceToDevice, 0);
    cudaMemcpyAsync(outv, v_cache, cacheBytes, cudaMemcpyDeviceToDevice, 0);

    init_invfreq_kernel<<<1, 128>>>();                             // launch 1

    const long long BIG = 1LL << 30;
    dim3 tb(32, 8);

    // x -> bf16 pair
    convert_pair_kernel<<<512, 256>>>(x, pxh, pxl, (long long)BT * HID);  // 2

    // qkv weights -> transposed bf16 pairs (launches 3,4,5)
    transpose_convert_kernel<<<dim3(2048/32, HID/32, 1), tb>>>(
        wq, pwth, pwtl, 2048, HID, 1, 0, 0, 0, 0);
    transpose_convert_kernel<<<dim3(1024/32, HID/32, 1), tb>>>(
        wk, pwth + 2048LL*HID, pwtl + 2048LL*HID, 1024, HID, 1, 0, 0, 0, 0);
    transpose_convert_kernel<<<dim3(1024/32, HID/32, 1), tb>>>(
        wv, pwth + 3072LL*HID, pwtl + 3072LL*HID, 1024, HID, 1, 0, 0, 0, 0);

    // QKV projection: [2048,4096] fp32   (launch 6 -> ncu captures this)
    mma_gemm<<<dim3(QKVN/GBN, BT/GBM, 1), 256, GEMM_SMEM>>>(
        pxh, pxl, pwth, pwtl, pqkv, nullptr, nullptr, HID, QKVN, 0,
        BIG,1,0,0,  BIG,1,0,0,  BIG,1,0,0);

    // wo transpose (deferred; needed only before out projection)
    transpose_convert_kernel<<<dim3(HID/32, 2048/32, 1), tb>>>(
        wo, pwoth, pwotl, HID, 2048, 1, 0, 0, 0, 0);

    // norm + rope + splits + cache scatter
    normrope_kernel<<<dim3(BT, 16), 128>>>(qw, kw, posp, cip, outk, outv);

    // V^T bf16 pairs: per z=(b,kv): src [1024,256] in g_qkv -> [256,1024]
    transpose_convert_kernel<<<dim3(HD/32, TT/32, BB*NKV), tb>>>(
        pqkv, pvth, pvtl, QKVN, TT,
        NKV, (long long)TT*QKVN, HD, 3072, (long long)HD*TT);

    // scores: z=(b,h): Q[1024,256] @ K[1024,256]^T -> fp32 [1024,1024]
    mma_gemm<<<dim3(TT/GBN, TT/GBM, BB*NH), 256, GEMM_SMEM>>>(
        pqph, pqpl, pkph, pkpl, psc, nullptr, nullptr, HD, TT, 0,
        BIG,1,0,(long long)TT*HD,
        NH,2,(long long)NKV*TT*HD,(long long)TT*HD,
        BIG,1,0,(long long)TT*TT);

    // softmax -> P pairs
    softmax_kernel<<<(long long)BB*NH*TT, 256>>>();

    // PV: z=(b,h): P[1024,1024] @ V^T[256,1024]^T -> ctx pairs [bt, h*256+d]
    mma_gemm<<<dim3(HD/GBN, TT/GBM, BB*NH), 256, GEMM_SMEM>>>(
        pph, ppl, pvth, pvtl, nullptr, pcth, pctl, TT, NH*HD, 1,
        BIG,1,0,(long long)TT*TT,
        NH,2,(long long)NKV*HD*TT,(long long)HD*TT,
        NH,1,(long long)TT*NH*HD,(long long)HD);

    // out projection: ctx [2048,2048] @ wo^T -> out fp32 [2048,2560]
    mma_gemm<<<dim3(HID/GBN, BT/GBM, 1), 256, GEMM_SMEM>>>(
        pcth, pctl, pwoth, pwotl, out, nullptr, nullptr, NH*HD, HID, 0,
        BIG,1,0,0,  BIG,1,0,0,  BIG,1,0,0);
}

// round 8
// speedup vs baseline: 3.0541x; 1.0125x over previous
#include <cuda_runtime.h>
#include <cuda_bf16.h>
#include <cstdint>
#include <math.h>

// ---------------------------------------------------------------------------
// Gemma3Attention on GB300 (compute_103 target -> mma.sync HMMA bf16 with
// hi/lo split, fp32 accumulate).
// B=2, T=1024, S=4096, HIDDEN=2560, HEADS=8, KV_HEADS=4, HEAD_DIM=256.
// valid keys == [cache_index, cache_index+T) exactly -> attention only over
// the freshly projected K/V tokens.
// GEMM config: 128x256 block tile, 512 threads, NSTAGE=2, 120KB SMEM.
// ---------------------------------------------------------------------------
#define BB   2
#define TT   1024
#define SSZ  4096
#define HID  2560
#define NH   8
#define NKV  4
#define HD   256
#define BT   (BB * TT)            // 2048
#define QKVN 4096                 // 2048 q + 1024 k + 1024 v cols
#define ATT_SCALE 0.0625f

// ---------------- scratch (device globals) ---------------------------------
__device__ float          g_qkv [(long long)BT * QKVN];        // fp32 qkv proj
__device__ __nv_bfloat16  g_xh  [(long long)BT * HID];
__device__ __nv_bfloat16  g_xl  [(long long)BT * HID];
__device__ __nv_bfloat16  g_wth [(long long)QKVN * HID];       // [wq;wk;wv]^T
__device__ __nv_bfloat16  g_wtl [(long long)QKVN * HID];
__device__ __nv_bfloat16  g_woth[(long long)HID * (NH * HD)];  // wo^T
__device__ __nv_bfloat16  g_wotl[(long long)HID * (NH * HD)];
__device__ __nv_bfloat16  g_qph [(long long)BB * NH  * TT * HD];
__device__ __nv_bfloat16  g_qpl [(long long)BB * NH  * TT * HD];
__device__ __nv_bfloat16  g_kph [(long long)BB * NKV * TT * HD];
__device__ __nv_bfloat16  g_kpl [(long long)BB * NKV * TT * HD];
__device__ __nv_bfloat16  g_vth [(long long)BB * NKV * HD * TT];  // V^T
__device__ __nv_bfloat16  g_vtl [(long long)BB * NKV * HD * TT];
__device__ float          g_sc  [(long long)BB * NH * TT * TT];
__device__ __nv_bfloat16  g_ph  [(long long)BB * NH * TT * TT];
__device__ __nv_bfloat16  g_pl  [(long long)BB * NH * TT * TT];
__device__ __nv_bfloat16  g_ctxh[(long long)BT * NH * HD];
__device__ __nv_bfloat16  g_ctxl[(long long)BT * NH * HD];
__device__ float          g_invfreq[128];

// ---------------------------------------------------------------------------
// helpers
// ---------------------------------------------------------------------------
__device__ __forceinline__ uint32_t smem_u32(const void* p) {
    uint32_t a;
    asm("{ .reg .u64 t; cvta.to.shared.u64 t, %1; cvt.u32.u64 %0, t; }"
        : "=r"(a) : "l"(p));
    return a;
}
__device__ __forceinline__ void cp16(uint32_t s, const void* g) {
    asm volatile("cp.async.cg.shared.global [%0], [%1], 16;" :: "r"(s), "l"(g));
}
#define CP_COMMIT() asm volatile("cp.async.commit_group;")
#define CP_WAIT(n)  asm volatile("cp.async.wait_group %0;" :: "n"(n))

__device__ __forceinline__ void ldm_x4(uint32_t* r, uint32_t addr) {
    asm volatile("ldmatrix.sync.aligned.m8n8.x4.shared.b16 {%0,%1,%2,%3}, [%4];"
        : "=r"(r[0]), "=r"(r[1]), "=r"(r[2]), "=r"(r[3]) : "r"(addr));
}
__device__ __forceinline__ void mma_bf16(float* d, const uint32_t* a,
                                         const uint32_t* b) {
    asm volatile(
        "mma.sync.aligned.m16n8k16.row.col.f32.bf16.bf16.f32 "
        "{%0,%1,%2,%3}, {%4,%5,%6,%7}, {%8,%9}, {%0,%1,%2,%3};"
        : "+f"(d[0]), "+f"(d[1]), "+f"(d[2]), "+f"(d[3])
        : "r"(a[0]), "r"(a[1]), "r"(a[2]), "r"(a[3]), "r"(b[0]), "r"(b[1]));
}
__device__ __forceinline__ void split2(float v, __nv_bfloat16& h, __nv_bfloat16& l) {
    h = __float2bfloat16(v);
    l = __float2bfloat16(v - __bfloat162float(h));
}

// ---------------------------------------------------------------------------
// HMMA GEMM:  C[M,N] = A[M,K] @ B[N,K]^T, A/B bf16 hi+lo (K-major), fp32 acc.
// C = Ah*Bh + Ah*Bl + Al*Bh  (Al*Bl dropped: ~2^-18 rel)
// Block 128x256, 16 warps (2Mx8N), warp 64x32, K-chunk 32, double-buffered
// cp.async (2 stages x 60KB = 120KB). SMEM row pitch 80B -> ldmatrix
// conflict-free (mod-128 distinct).
// Batch z: off = (z/div)*s1 + ((z%div)/g)*s2  (elements)
// outPair=0: fp32 -> Cf ; outPair=1: bf16 hi/lo -> Ch/Cl
// ---------------------------------------------------------------------------
#define GBM 128
#define GBN 256
#define GBK 32
#define PITCH 80
#define ATILE_B (128 * PITCH)         // 10240
#define BTILE_B (256 * PITCH)         // 20480
#define OFF_AH 0
#define OFF_AL ATILE_B                // 10240
#define OFF_BH (2 * ATILE_B)          // 20480
#define OFF_BL (2 * ATILE_B + BTILE_B)// 40960
#define STAGE  (2 * ATILE_B + 2 * BTILE_B)  // 61440
#define GEMM_SMEM (2 * STAGE)         // 122880

__global__ __launch_bounds__(512, 1) void mma_gemm(
    const __nv_bfloat16* __restrict__ Ah, const __nv_bfloat16* __restrict__ Al,
    const __nv_bfloat16* __restrict__ Bh, const __nv_bfloat16* __restrict__ Bl,
    float* __restrict__ Cf, __nv_bfloat16* __restrict__ Ch, __nv_bfloat16* __restrict__ Cl,
    int K, int ldc, int outPair,
    long long aDiv, long long aG, long long aS1, long long aS2,
    long long bDiv, long long bG, long long bS1, long long bS2,
    long long cDiv, long long cG, long long cS1, long long cS2)
{
    extern __shared__ char smem[];
    uint32_t sb = smem_u32(smem);
    int tid = threadIdx.x, wid = tid >> 5, lane = tid & 31;
    int warpM = wid >> 3, warpN = wid & 7;

    long long z = blockIdx.z;
    long long offA = (z / aDiv) * aS1 + ((z % aDiv) / aG) * aS2;
    long long offB = (z / bDiv) * bS1 + ((z % bDiv) / bG) * bS2;
    long long offC = (z / cDiv) * cS1 + ((z % cDiv) / cG) * cS2;

    int brow = blockIdx.y * GBM;
    int bcol = blockIdx.x * GBN;
    long long rowB = (long long)K * 2;

    const char* srcAh = (const char*)(Ah + offA) + (long long)brow * rowB;
    const char* srcAl = (const char*)(Al + offA) + (long long)brow * rowB;
    const char* srcBh = (const char*)(Bh + offB) + (long long)bcol * rowB;
    const char* srcBl = (const char*)(Bl + offB) + (long long)bcol * rowB;

    // loader (512 threads): A 128 rows x 64B (1 cp16/thread/tile),
    // B 256 rows x 64B (2 cp16/thread/tile); one commit group per chunk.
    auto load_chunk = [&](int chunk, int stage) {
        uint32_t st = sb + stage * STAGE;
        long long kb = (long long)chunk * GBK * 2;
        {
            int r = tid >> 2, c = (tid & 3) * 16;
            long long go = (long long)r * rowB + kb + c;
            uint32_t so = r * PITCH + c;
            cp16(st + OFF_AH + so, srcAh + go);
            cp16(st + OFF_AL + so, srcAl + go);
        }
        #pragma unroll
        for (int it = 0; it < 2; it++) {
            int within = it * 512 + tid;
            int r = within >> 2, c = (within & 3) * 16;
            long long go = (long long)r * rowB + kb + c;
            uint32_t so = r * PITCH + c;
            cp16(st + OFF_BH + so, srcBh + go);
            cp16(st + OFF_BL + so, srcBl + go);
        }
        CP_COMMIT();
    };

    float acc[4][4][4];
    #pragma unroll
    for (int i = 0; i < 4; i++)
        #pragma unroll
        for (int j = 0; j < 4; j++)
            #pragma unroll
            for (int k = 0; k < 4; k++) acc[i][j][k] = 0.0f;

    int nCh = K / GBK;
    load_chunk(0, 0);

    for (int i = 0; i < nCh; i++) {
        if (i + 1 < nCh) { load_chunk(i + 1, (i + 1) & 1); CP_WAIT(1); }
        else             { CP_WAIT(0); }
        __syncthreads();

        uint32_t st = sb + (i & 1) * STAGE;
        uint32_t baseAh = st + OFF_AH + warpM * 64 * PITCH;
        uint32_t baseAl = st + OFF_AL + warpM * 64 * PITCH;
        uint32_t baseBh = st + OFF_BH + warpN * 32 * PITCH;
        uint32_t baseBl = st + OFF_BL + warpN * 32 * PITCH;

        int aRow = lane & 15;
        int aCol = (lane >> 4) * 16;
        int bRow = (lane >> 4) * 8 + (lane & 7);
        int bCol = ((lane >> 3) & 1) * 16;

        #pragma unroll
        for (int s = 0; s < 2; s++) {     // two k16 steps per 32-chunk
            uint32_t bHf[4][2], bLf[4][2];
            #pragma unroll
            for (int np = 0; np < 2; np++) {
                uint32_t r4[4];
                uint32_t off = (np * 16 + bRow) * PITCH + s * 32 + bCol;
                ldm_x4(r4, baseBh + off);
                bHf[np*2][0] = r4[0]; bHf[np*2][1] = r4[1];
                bHf[np*2+1][0] = r4[2]; bHf[np*2+1][1] = r4[3];
                ldm_x4(r4, baseBl + off);
                bLf[np*2][0] = r4[0]; bLf[np*2][1] = r4[1];
                bLf[np*2+1][0] = r4[2]; bLf[np*2+1][1] = r4[3];
            }
            #pragma unroll
            for (int mg = 0; mg < 4; mg++) {
                uint32_t aH[4], aL[4];
                uint32_t off = (mg * 16 + aRow) * PITCH + s * 32 + aCol;
                ldm_x4(aH, baseAh + off);
                ldm_x4(aL, baseAl + off);
                #pragma unroll
                for (int nt = 0; nt < 4; nt++) {
                    mma_bf16(acc[mg][nt], aH, bHf[nt]);
                    mma_bf16(acc[mg][nt], aH, bLf[nt]);
                    mma_bf16(acc[mg][nt], aL, bHf[nt]);
                }
            }
        }
        __syncthreads();
    }

    // ---- epilogue: direct register -> gmem ----
    #pragma unroll
    for (int mg = 0; mg < 4; mg++) {
        #pragma unroll
        for (int nt = 0; nt < 4; nt++) {
            int r0 = brow + warpM * 64 + mg * 16 + (lane >> 2);
            int c  = bcol + warpN * 32 + nt * 8 + (lane & 3) * 2;
            float* a4 = acc[mg][nt];
            if (!outPair) {
                *(float2*)(Cf + offC + (long long)r0 * ldc + c) =
                    make_float2(a4[0], a4[1]);
                *(float2*)(Cf + offC + (long long)(r0 + 8) * ldc + c) =
                    make_float2(a4[2], a4[3]);
            } else {
                #pragma unroll
                for (int hh = 0; hh < 2; hh++) {
                    __nv_bfloat16 h0, l0, h1, l1;
                    split2(a4[hh * 2 + 0], h0, l0);
                    split2(a4[hh * 2 + 1], h1, l1);
                    uint32_t hw = (uint32_t)*(uint16_t*)&h0 |
                                  ((uint32_t)*(uint16_t*)&h1 << 16);
                    uint32_t lw = (uint32_t)*(uint16_t*)&l0 |
                                  ((uint32_t)*(uint16_t*)&l1 << 16);
                    long long o = offC + (long long)(r0 + hh * 8) * ldc + c;
                    *(uint32_t*)(Ch + o) = hw;
                    *(uint32_t*)(Cl + o) = lw;
                }
            }
        }
    }
}

// ---------------------------------------------------------------------------
// fp32 -> bf16 hi/lo elementwise (for x)
// ---------------------------------------------------------------------------
__global__ void convert_pair_kernel(const float* __restrict__ src,
                                    __nv_bfloat16* __restrict__ dh,
                                    __nv_bfloat16* __restrict__ dl, long long n)
{
    long long i = (long long)(blockIdx.x) * blockDim.x + threadIdx.x;
    long long stride = (long long)gridDim.x * blockDim.x;
    for (; i * 4 < n; i += stride) {
        float4 v = ((const float4*)src)[i];
        __nv_bfloat16 h, l;
        split2(v.x, h, l); dh[i*4+0] = h; dl[i*4+0] = l;
        split2(v.y, h, l); dh[i*4+1] = h; dl[i*4+1] = l;
        split2(v.z, h, l); dh[i*4+2] = h; dl[i*4+2] = l;
        split2(v.w, h, l); dh[i*4+3] = h; dl[i*4+3] = l;
    }
}

// ---------------------------------------------------------------------------
// Combined QKV weight transpose+convert: [wq|wk|wv] columns -> g_wth/g_wtl
// rows. grid (QKVN/32, HID/32), block (32,8).
// ---------------------------------------------------------------------------
__global__ void transpose_qkv_kernel(
    const float* __restrict__ wq, const float* __restrict__ wk,
    const float* __restrict__ wv,
    __nv_bfloat16* __restrict__ dh, __nv_bfloat16* __restrict__ dl)
{
    __shared__ float tile[32][33];
    int tx = threadIdx.x, ty = threadIdx.y;
    int c0 = blockIdx.x * 32;        // global output-row block (qkv col)
    int r0 = blockIdx.y * 32;        // hidden-dim block

    const float* s; int lds, sc0;
    if (c0 < 2048)      { s = wq; lds = 2048; sc0 = c0; }
    else if (c0 < 3072) { s = wk; lds = 1024; sc0 = c0 - 2048; }
    else                { s = wv; lds = 1024; sc0 = c0 - 3072; }

    #pragma unroll
    for (int i = 0; i < 4; i++) {
        int r = r0 + ty + i * 8;
        tile[ty + i * 8][tx] = s[(long long)r * lds + sc0 + tx];
    }
    __syncthreads();
    #pragma unroll
    for (int i = 0; i < 4; i++) {
        int dr = c0 + ty + i * 8;
        int dc = r0 + tx;
        float v = tile[tx][ty + i * 8];
        __nv_bfloat16 h, l;
        split2(v, h, l);
        dh[(long long)dr * HID + dc] = h;
        dl[(long long)dr * HID + dc] = l;
    }
}

// ---------------------------------------------------------------------------
// Transpose + convert: src fp32 [R,C] (row stride lds) -> dst bf16 pair [C,R]
// (row stride ldd).  Per-z: srcOff = (z/div)*s1 + (z%div)*s2 + add; dst z*dstZ.
// ---------------------------------------------------------------------------
__global__ void transpose_convert_kernel(
    const float* __restrict__ src, __nv_bfloat16* __restrict__ dh,
    __nv_bfloat16* __restrict__ dl, int lds, int ldd,
    long long sDiv, long long sS1, long long sS2, long long sAdd, long long dstZ)
{
    __shared__ float tile[32][33];
    long long z = blockIdx.z;
    const float* s = src + (z / sDiv) * sS1 + (z % sDiv) * sS2 + sAdd;
    long long doff = z * dstZ;

    int tx = threadIdx.x, ty = threadIdx.y;
    int c0 = blockIdx.x * 32, r0 = blockIdx.y * 32;
    #pragma unroll
    for (int i = 0; i < 4; i++) {
        int r = r0 + ty + i * 8;
        tile[ty + i * 8][tx] = s[(long long)r * lds + c0 + tx];
    }
    __syncthreads();
    #pragma unroll
    for (int i = 0; i < 4; i++) {
        int dr = c0 + ty + i * 8;
        int dc = r0 + tx;
        float v = tile[tx][ty + i * 8];
        __nv_bfloat16 h, l;
        split2(v, h, l);
        dh[doff + (long long)dr * ldd + dc] = h;
        dl[doff + (long long)dr * ldd + dc] = l;
    }
}

// ---------------------------------------------------------------------------
__global__ void init_invfreq_kernel() {
    int j = threadIdx.x;
    g_invfreq[j] = (float)pow(10000.0, -(double)j / 128.0);
}

// ---------------------------------------------------------------------------
// RMSNorm + RoPE + split-convert + cache scatter.
// grid (BT, 16): y 0..7 Q heads, 8..11 K heads, 12..15 V cache copy.
// ---------------------------------------------------------------------------
__device__ __forceinline__ float block_sum_128(float v) {
    #pragma unroll
    for (int o = 16; o > 0; o >>= 1) v += __shfl_xor_sync(0xffffffffu, v, o);
    __shared__ float sh[4];
    int w = threadIdx.x >> 5;
    if ((threadIdx.x & 31) == 0) sh[w] = v;
    __syncthreads();
    return sh[0] + sh[1] + sh[2] + sh[3];
}

__global__ void normrope_kernel(
    const float* __restrict__ qw, const float* __restrict__ kw,
    const int* __restrict__ posp, const int* __restrict__ cip,
    float* __restrict__ outk, float* __restrict__ outv)
{
    int bt  = blockIdx.x;
    int b   = bt / TT, t = bt - b * TT;
    int hsl = blockIdx.y;
    int tid = threadIdx.x;

    if (hsl >= NH + NKV) {                 // V: cache copy only
        int h = hsl - NH - NKV;
        int ci = *cip;
        const float* src = g_qkv + (long long)bt * QKVN + 3072 + h * HD;
        float* dc = outv + (((long long)b * NKV + h) * SSZ + ci + t) * HD;
        dc[tid] = src[tid]; dc[tid + 128] = src[tid + 128];
        return;
    }

    bool isQ = (hsl < NH);
    int  h   = isQ ? hsl : hsl - NH;
    int  col = isQ ? h * HD : 2048 + h * HD;
    const float* src = g_qkv + (long long)bt * QKVN + col;
    const float* w = isQ ? qw : kw;

    float v1 = src[tid], v2 = src[tid + 128];
    float ss = block_sum_128(v1 * v1 + v2 * v2);
    float r  = rsqrtf(ss * (1.0f / HD) + 1e-6f);
    float x1 = v1 * r * (1.0f + w[tid]);
    float x2 = v2 * r * (1.0f + w[tid + 128]);

    int pos = *posp + t;
    float ang = (float)pos * g_invfreq[tid];
    double da  = (double)ang;
    double red = da - floor(da * 0.159154943091895335768883763373) *
                      6.283185307179586476925286766559;
    float c = cosf((float)red), s = sinf((float)red);

    float o1 = x1 * c - x2 * s;
    float o2 = x2 * c + x1 * s;

    __nv_bfloat16 h1, l1, h2, l2;
    if (isQ) {
        o1 *= ATT_SCALE; o2 *= ATT_SCALE;
        split2(o1, h1, l1); split2(o2, h2, l2);
        long long base = (((long long)b * NH + h) * TT + t) * HD;
        g_qph[base + tid] = h1;       g_qpl[base + tid] = l1;
        g_qph[base + tid + 128] = h2; g_qpl[base + tid + 128] = l2;
    } else {
        split2(o1, h1, l1); split2(o2, h2, l2);
        long long base = (((long long)b * NKV + h) * TT + t) * HD;
        g_kph[base + tid] = h1;       g_kpl[base + tid] = l1;
        g_kph[base + tid + 128] = h2; g_kpl[base + tid + 128] = l2;
        int ci = *cip;
        float* dc = outk + (((long long)b * NKV + h) * SSZ + ci + t) * HD;
        dc[tid] = o1; dc[tid + 128] = o2;
    }
}

// ---------------------------------------------------------------------------
// Row softmax over 1024 keys, writes P as bf16 hi/lo pairs.
// ---------------------------------------------------------------------------
__global__ __launch_bounds__(256) void softmax_kernel()
{
    long long row = blockIdx.x;
    const float* p = g_sc + row * TT;
    int tid = threadIdx.x;

    float4 v = ((const float4*)p)[tid];
    float m = fmaxf(fmaxf(v.x, v.y), fmaxf(v.z, v.w));
    #pragma unroll
    for (int o = 16; o > 0; o >>= 1) m = fmaxf(m, __shfl_xor_sync(0xffffffffu, m, o));
    __shared__ float sm[8];
    int w = tid >> 5;
    if ((tid & 31) == 0) sm[w] = m;
    __syncthreads();
    m = fmaxf(fmaxf(fmaxf(sm[0], sm[1]), fmaxf(sm[2], sm[3])),
              fmaxf(fmaxf(sm[4], sm[5]), fmaxf(sm[6], sm[7])));

    float e0 = expf(v.x - m), e1 = expf(v.y - m), e2 = expf(v.z - m), e3 = expf(v.w - m);
    float sum = e0 + e1 + e2 + e3;
    #pragma unroll
    for (int o = 16; o > 0; o >>= 1) sum += __shfl_xor_sync(0xffffffffu, sum, o);
    __shared__ float s2[8];
    if ((tid & 31) == 0) s2[w] = sum;
    __syncthreads();
    sum = s2[0] + s2[1] + s2[2] + s2[3] + s2[4] + s2[5] + s2[6] + s2[7];

    float inv = 1.0f / sum;
    float pv[4] = {e0 * inv, e1 * inv, e2 * inv, e3 * inv};
    uint32_t hw[2], lw[2];
    #pragma unroll
    for (int j = 0; j < 2; j++) {
        __nv_bfloat16 h0, l0, h1, l1;
        split2(pv[2 * j], h0, l0);
        split2(pv[2 * j + 1], h1, l1);
        hw[j] = (uint32_t)*(uint16_t*)&h0 | ((uint32_t)*(uint16_t*)&h1 << 16);
        lw[j] = (uint32_t)*(uint16_t*)&l0 | ((uint32_t)*(uint16_t*)&l1 << 16);
    }
    long long o = row * TT + tid * 4;
    *(uint2*)(g_ph + o) = make_uint2(hw[0], hw[1]);
    *(uint2*)(g_pl + o) = make_uint2(lw[0], lw[1]);
}

// ---------------------------------------------------------------------------
// kernel_launch
// Kernel order: init(k1), convert(k2), t_qkv(k3), mma_gemm(k4) -- k4 is
// node #6 after the two memcpys, which is what ncu -s 5 -c 1 captures.
// ---------------------------------------------------------------------------
extern "C" void kernel_launch(void* const* d_in, const int* in_sizes, int n_in,
                              void* d_out, int out_size)
{
    const float* x       = (const float*)d_in[0];
    const float* k_cache = (const float*)d_in[1];
    const float* v_cache = (const float*)d_in[2];
    const float* wq      = (const float*)d_in[3];
    const float* wk      = (const float*)d_in[4];
    const float* wv      = (const float*)d_in[5];
    const float* wo      = (const float*)d_in[6];
    const float* qw      = (const float*)d_in[7];
    const float* kw      = (const float*)d_in[8];
    const int*   posp    = (const int*)d_in[9];
    const int*   cip     = (const int*)d_in[10];

    float* out  = (float*)d_out;
    float* outk = out  + (long long)BB * TT * HID;
    float* outv = outk + (long long)BB * NKV * SSZ * HD;

    float *pqkv, *psc;
    __nv_bfloat16 *pxh, *pxl, *pwth, *pwtl, *pwoth, *pwotl;
    __nv_bfloat16 *pqph, *pqpl, *pkph, *pkpl, *pvth, *pvtl, *pph, *ppl, *pcth, *pctl;
    cudaGetSymbolAddress((void**)&pqkv,  g_qkv);
    cudaGetSymbolAddress((void**)&psc,   g_sc);
    cudaGetSymbolAddress((void**)&pxh,   g_xh);
    cudaGetSymbolAddress((void**)&pxl,   g_xl);
    cudaGetSymbolAddress((void**)&pwth,  g_wth);
    cudaGetSymbolAddress((void**)&pwtl,  g_wtl);
    cudaGetSymbolAddress((void**)&pwoth, g_woth);
    cudaGetSymbolAddress((void**)&pwotl, g_wotl);
    cudaGetSymbolAddress((void**)&pqph,  g_qph);
    cudaGetSymbolAddress((void**)&pqpl,  g_qpl);
    cudaGetSymbolAddress((void**)&pkph,  g_kph);
    cudaGetSymbolAddress((void**)&pkpl,  g_kpl);
    cudaGetSymbolAddress((void**)&pvth,  g_vth);
    cudaGetSymbolAddress((void**)&pvtl,  g_vtl);
    cudaGetSymbolAddress((void**)&pph,   g_ph);
    cudaGetSymbolAddress((void**)&ppl,   g_pl);
    cudaGetSymbolAddress((void**)&pcth,  g_ctxh);
    cudaGetSymbolAddress((void**)&pctl,  g_ctxl);

    cudaFuncSetAttribute(mma_gemm, cudaFuncAttributeMaxDynamicSharedMemorySize, GEMM_SMEM);

    // cache copies (new slice overwritten later in-stream)
    size_t cacheBytes = sizeof(float) * (size_t)BB * NKV * SSZ * HD;
    cudaMemcpyAsync(outk, k_cache, cacheBytes, cudaMemcpyDeviceToDevice, 0);
    cudaMemcpyAsync(outv, v_cache, cacheBytes, cudaMemcpyDeviceToDevice, 0);

    init_invfreq_kernel<<<1, 128>>>();                                    // k1

    const long long BIG = 1LL << 30;
    dim3 tb(32, 8);

    // x -> bf16 pair
    convert_pair_kernel<<<512, 256>>>(x, pxh, pxl, (long long)BT * HID);  // k2

    // combined qkv weight transpose                                        k3
    transpose_qkv_kernel<<<dim3(QKVN/32, HID/32), tb>>>(wq, wk, wv, pwth, pwtl);

    // QKV projection: [2048,4096] fp32                                     k4
    mma_gemm<<<dim3(QKVN/GBN, BT/GBM, 1), 512, GEMM_SMEM>>>(
        pxh, pxl, pwth, pwtl, pqkv, nullptr, nullptr, HID, QKVN, 0,
        BIG,1,0,0,  BIG,1,0,0,  BIG,1,0,0);

    // wo transpose (deferred; needed only before out projection)
    transpose_convert_kernel<<<dim3(HID/32, 2048/32, 1), tb>>>(
        wo, pwoth, pwotl, HID, 2048, 1, 0, 0, 0, 0);

    // norm + rope + splits + cache scatter
    normrope_kernel<<<dim3(BT, 16), 128>>>(qw, kw, posp, cip, outk, outv);

    // V^T bf16 pairs: per z=(b,kv): src [1024,256] in g_qkv -> [256,1024]
    transpose_convert_kernel<<<dim3(HD/32, TT/32, BB*NKV), tb>>>(
        pqkv, pvth, pvtl, QKVN, TT,
        NKV, (long long)TT*QKVN, HD, 3072, (long long)HD*TT);

    // scores: z=(b,h): Q[1024,256] @ K[1024,256]^T -> fp32 [1024,1024]
    mma_gemm<<<dim3(TT/GBN, TT/GBM, BB*NH), 512, GEMM_SMEM>>>(
        pqph, pqpl, pkph, pkpl, psc, nullptr, nullptr, HD, TT, 0,
        BIG,1,0,(long long)TT*HD,
        NH,2,(long long)NKV*TT*HD,(long long)TT*HD,
        BIG,1,0,(long long)TT*TT);

    // softmax -> P pairs
    softmax_kernel<<<(long long)BB*NH*TT, 256>>>();

    // PV: z=(b,h): P[1024,1024] @ V^T[256,1024]^T -> ctx pairs [bt, h*256+d]
    mma_gemm<<<dim3(HD/GBN, TT/GBM, BB*NH), 512, GEMM_SMEM>>>(
        pph, ppl, pvth, pvtl, nullptr, pcth, pctl, TT, NH*HD, 1,
        BIG,1,0,(long long)TT*TT,
        NH,2,(long long)NKV*HD*TT,(long long)HD*TT,
        NH,1,(long long)TT*NH*HD,(long long)HD);

    // out projection: ctx [2048,2048] @ wo^T -> out fp32 [2048,2560]
    mma_gemm<<<dim3(HID/GBN, BT/GBM, 1), 512, GEMM_SMEM>>>(
        pcth, pctl, pwoth, pwotl, out, nullptr, nullptr, NH*HD, HID, 0,
        BIG,1,0,0,  BIG,1,0,0,  BIG,1,0,0);
}